// round 1
// baseline (speedup 1.0000x reference)
#include <cuda_runtime.h>
#include <cuda_bf16.h>
#include <math.h>

#define Bv 2
#define Cv 64
#define Hv 80
#define Wv 80
#define Nv 6400
#define NQ 1600
#define NHWf 12800.0f
#define EPSV 1e-5f

// ---------------- scratch ----------------
// t0, feat1, vb, pvd, sab, scb, bn2o : 7 * 819200
// qb, kb : 2 * 204800 ; pqd, pkd : 2 * 102400
// attn 8192 ; ps 4096 ; pss 4096 ; scale 64 ; shift 64
#define OFF_T0     0
#define OFF_FEAT1  (OFF_T0   + Bv*Cv*Nv)
#define OFF_VB     (OFF_FEAT1+ Bv*Cv*Nv)
#define OFF_PVD    (OFF_VB   + Bv*Cv*Nv)
#define OFF_SAB    (OFF_PVD  + Bv*Cv*Nv)
#define OFF_SCB    (OFF_SAB  + Bv*Cv*Nv)
#define OFF_BN2O   (OFF_SCB  + Bv*Cv*Nv)
#define OFF_QB     (OFF_BN2O + Bv*Cv*Nv)
#define OFF_KB     (OFF_QB   + Bv*Cv*NQ)
#define OFF_PQD    (OFF_KB   + Bv*Cv*NQ)
#define OFF_PKD    (OFF_PQD  + Bv*8*Nv)
#define OFF_ATTN   (OFF_PKD  + Bv*8*Nv)
#define OFF_PS     (OFF_ATTN + Bv*Cv*Cv)
#define OFF_PSS    (OFF_PS   + 64*64)
#define OFF_SCALE  (OFF_PSS  + 64*64)
#define OFF_SHIFT  (OFF_SCALE+ 64)
#define BUF_TOTAL  (OFF_SHIFT+ 64)

__device__ float g_buf[BUF_TOTAL];

// ---------------- conv3x3 (pad=1, no bias) + per-block BN partial stats ----------------
// grid (5,5,B*C), block (16,16). Partial slot = b*25 + by*5 + bx  (50 slots/channel)
__global__ void conv3x3_kernel(const float* __restrict__ in, const float* __restrict__ w,
                               float* __restrict__ out, float* __restrict__ ps,
                               float* __restrict__ pss) {
    __shared__ float wsm[576];
    __shared__ float tile[18 * 18];
    __shared__ float red[256];
    int bz = blockIdx.z;
    int b = bz >> 6, co = bz & 63;
    int t = threadIdx.y * 16 + threadIdx.x;
    for (int i = t; i < 576; i += 256) wsm[i] = w[co * 576 + i];
    int oy0 = blockIdx.y * 16, ox0 = blockIdx.x * 16;
    const float* inb = in + (long)b * Cv * Nv;
    float acc = 0.f;
    for (int ci = 0; ci < 64; ci++) {
        __syncthreads();
        for (int i = t; i < 324; i += 256) {
            int r = i / 18, c2 = i % 18;
            int gy = oy0 + r - 1, gx = ox0 + c2 - 1;
            float v = 0.f;
            if (gy >= 0 && gy < Hv && gx >= 0 && gx < Wv) v = inb[ci * Nv + gy * Wv + gx];
            tile[i] = v;
        }
        __syncthreads();
        const float* wc = wsm + ci * 9;
#pragma unroll
        for (int ky = 0; ky < 3; ky++)
#pragma unroll
            for (int kx = 0; kx < 3; kx++)
                acc += wc[ky * 3 + kx] * tile[(threadIdx.y + ky) * 18 + threadIdx.x + kx];
    }
    out[(long)bz * Nv + (oy0 + threadIdx.y) * Wv + ox0 + threadIdx.x] = acc;

    int slot = b * 25 + blockIdx.y * 5 + blockIdx.x;
    red[t] = acc;
    __syncthreads();
    for (int st = 128; st > 0; st >>= 1) { if (t < st) red[t] += red[t + st]; __syncthreads(); }
    if (t == 0) ps[co * 64 + slot] = red[0];
    __syncthreads();
    red[t] = acc * acc;
    __syncthreads();
    for (int st = 128; st > 0; st >>= 1) { if (t < st) red[t] += red[t + st]; __syncthreads(); }
    if (t == 0) pss[co * 64 + slot] = red[0];
}

// ---------------- BN finalize: scale/shift from partial sums ----------------
__global__ void bn_finalize(const float* __restrict__ ps, const float* __restrict__ pss,
                            const float* __restrict__ g, const float* __restrict__ bb,
                            float* __restrict__ scale, float* __restrict__ shift, int nslots) {
    int c = threadIdx.x;
    float s = 0.f, ss = 0.f;
    for (int i = 0; i < nslots; i++) { s += ps[c * 64 + i]; ss += pss[c * 64 + i]; }
    float m = s / NHWf;
    float var = ss / NHWf - m * m;
    float rs = rsqrtf(var + EPSV);
    float sc = g[c] * rs;
    scale[c] = sc;
    shift[c] = bb[c] - m * sc;
}

// ---------------- BN apply (+optional relu) ----------------
__global__ void bn_apply_kernel(const float* __restrict__ in, float* __restrict__ out,
                                const float* __restrict__ scale, const float* __restrict__ shift,
                                int relu) {
    int idx = blockIdx.x * 256 + threadIdx.x;
    int c = (idx / Nv) & 63;
    float v = in[idx] * scale[c] + shift[c];
    if (relu) v = fmaxf(v, 0.f);
    out[idx] = v;
}

// ---------------- conv 2x2 stride 2 (with bias) ----------------
// grid (B*C), block 256
__global__ void conv2x2_kernel(const float* __restrict__ in, const float* __restrict__ w,
                               const float* __restrict__ bias, float* __restrict__ out) {
    __shared__ float wsm[256];
    int bz = blockIdx.x;
    int b = bz >> 6, co = bz & 63;
    wsm[threadIdx.x] = w[co * 256 + threadIdx.x];
    __syncthreads();
    float bv = bias[co];
    const float* inb = in + (long)b * Cv * Nv;
    for (int p = threadIdx.x; p < NQ; p += 256) {
        int oy = p / 40, ox = p % 40;
        const float* ip = inb + (2 * oy) * Wv + 2 * ox;
        float acc = bv;
#pragma unroll 4
        for (int ci = 0; ci < 64; ci++) {
            const float* q = ip + ci * Nv;
            acc += wsm[ci * 4] * q[0] + wsm[ci * 4 + 1] * q[1]
                 + wsm[ci * 4 + 2] * q[Wv] + wsm[ci * 4 + 3] * q[Wv + 1];
        }
        out[(long)bz * NQ + p] = acc;
    }
}

// ---------------- conv1x1 (CO outputs, 64 inputs). weights optionally per-batch ----------------
// grid (B, 50), block 128. weights transposed in smem: wsm[ci*CO + co]
template <int CO>
__global__ void conv1x1_kernel(const float* __restrict__ in, const float* __restrict__ w,
                               int wstride, const float* __restrict__ bias,
                               float* __restrict__ out) {
    __shared__ float wsm[CO * 64];
    int b = blockIdx.x;
    int n = blockIdx.y * 128 + threadIdx.x;
    const float* wb = w + (long)b * wstride;
    for (int i = threadIdx.x; i < CO * 64; i += 128) {
        int co = i >> 6, ci = i & 63;
        wsm[ci * CO + co] = wb[i];
    }
    __syncthreads();
    float acc[CO];
#pragma unroll
    for (int co = 0; co < CO; co++) acc[co] = bias ? bias[co] : 0.f;
    const float* inb = in + (long)b * 64 * Nv + n;
    const float4* wsm4 = (const float4*)wsm;
#pragma unroll 4
    for (int ci = 0; ci < 64; ci++) {
        float xv = inb[ci * Nv];
#pragma unroll
        for (int c4 = 0; c4 < CO / 4; c4++) {
            float4 w4 = wsm4[ci * (CO / 4) + c4];
            acc[c4 * 4 + 0] += w4.x * xv;
            acc[c4 * 4 + 1] += w4.y * xv;
            acc[c4 * 4 + 2] += w4.z * xv;
            acc[c4 * 4 + 3] += w4.w * xv;
        }
    }
    float* ob = out + (long)b * CO * Nv + n;
#pragma unroll
    for (int co = 0; co < CO; co++) ob[co * Nv] = acc[co];
}

// ---------------- CAM energy + softmax ----------------
// grid (B*C), block 64. softmax(max-e) == exp(e_min - e)/sum
__global__ void cam_kernel(const float* __restrict__ q, const float* __restrict__ k,
                           float* __restrict__ attn) {
    __shared__ float qsm[NQ];
    __shared__ float er[64];
    __shared__ float pe[64];
    int b = blockIdx.x >> 6, c = blockIdx.x & 63;
    const float* qr = q + (long)(b * 64 + c) * NQ;
    for (int i = threadIdx.x; i < NQ; i += 64) qsm[i] = qr[i];
    __syncthreads();
    int d = threadIdx.x;
    const float4* kr = (const float4*)(k + (long)(b * 64 + d) * NQ);
    const float4* q4 = (const float4*)qsm;
    float s = 0.f;
#pragma unroll 4
    for (int i = 0; i < NQ / 4; i++) {
        float4 kv = kr[i];
        float4 qv = q4[i];
        s += qv.x * kv.x + qv.y * kv.y + qv.z * kv.z + qv.w * kv.w;
    }
    er[d] = s;
    __syncthreads();
    float mn = er[0];
    for (int i = 1; i < 64; i++) mn = fminf(mn, er[i]);
    float p = __expf(mn - s);
    pe[d] = p;
    __syncthreads();
    float sum = 0.f;
    for (int i = 0; i < 64; i++) sum += pe[i];
    attn[(long)(b * 64 + c) * 64 + d] = p / sum;
}

// ---------------- PAM: flash attention, d=8, dv=64 ----------------
// grid (50, 2, B): x = query tile (128 queries), y = channel half (32), z = batch
__global__ void pam_kernel(const float* __restrict__ pq, const float* __restrict__ pk,
                           const float* __restrict__ pv, float* __restrict__ sc) {
    __shared__ float ks[8 * 32];
    __shared__ float vs[32 * 32];
    int b = blockIdx.z, ch0 = blockIdx.y * 32;
    int n = blockIdx.x * 128 + threadIdx.x;
    const float* pqb = pq + (long)b * 8 * Nv;
    const float* pkb = pk + (long)b * 8 * Nv;
    const float* pvb = pv + (long)b * 64 * Nv;
    float qreg[8];
#pragma unroll
    for (int e = 0; e < 8; e++) qreg[e] = pqb[e * Nv + n];
    float o[32];
#pragma unroll
    for (int c = 0; c < 32; c++) o[c] = 0.f;
    float mi = -1e30f, li = 0.f;

    for (int m0 = 0; m0 < Nv; m0 += 32) {
        __syncthreads();
        for (int i = threadIdx.x; i < 256; i += 128) {
            int e = i >> 5, j = i & 31;
            ks[i] = pkb[e * Nv + m0 + j];
        }
        for (int i = threadIdx.x; i < 1024; i += 128) {
            int c = i >> 5, j = i & 31;
            vs[i] = pvb[(long)(ch0 + c) * Nv + m0 + j];
        }
        __syncthreads();
        float s[32];
        float tmax = -1e30f;
#pragma unroll
        for (int j = 0; j < 32; j++) {
            float t = 0.f;
#pragma unroll
            for (int e = 0; e < 8; e++) t += qreg[e] * ks[e * 32 + j];
            s[j] = t;
            tmax = fmaxf(tmax, t);
        }
        float mnew = fmaxf(mi, tmax);
        float corr = __expf(mi - mnew);
        li *= corr;
#pragma unroll
        for (int c = 0; c < 32; c++) o[c] *= corr;
#pragma unroll
        for (int j = 0; j < 32; j++) { s[j] = __expf(s[j] - mnew); li += s[j]; }
#pragma unroll
        for (int j4 = 0; j4 < 8; j4++) {
            float p0 = s[j4 * 4], p1 = s[j4 * 4 + 1], p2 = s[j4 * 4 + 2], p3 = s[j4 * 4 + 3];
#pragma unroll
            for (int c = 0; c < 32; c++) {
                float4 v4 = *(const float4*)&vs[c * 32 + j4 * 4];
                o[c] += p0 * v4.x + p1 * v4.y + p2 * v4.z + p3 * v4.w;
            }
        }
        mi = mnew;
    }
    float inv = 1.f / li;
#pragma unroll
    for (int c = 0; c < 32; c++)
        sc[(long)(b * 64 + ch0 + c) * Nv + n] = o[c] * inv;
}

// ---------------- feat_sum + BN2 partial stats ----------------
// grid (B*C), block 256. slot = b (2 slots/channel)
__global__ void fsum_kernel(const float* __restrict__ sa, const float* __restrict__ sc,
                            const float* __restrict__ f1, const float* __restrict__ gamma1,
                            const float* __restrict__ gamma2, float* __restrict__ out,
                            float* __restrict__ ps, float* __restrict__ pss) {
    __shared__ float red[256];
    int bz = blockIdx.x;
    int b = bz >> 6, c = bz & 63;
    float g1 = gamma1[0], g2 = gamma2[0];
    long base = (long)bz * Nv;
    float s = 0.f, ss = 0.f;
    for (int p = threadIdx.x; p < Nv; p += 256) {
        float v = g1 * sa[base + p] + g2 * sc[base + p] + f1[base + p];
        out[base + p] = v;
        s += v;
        ss += v * v;
    }
    int t = threadIdx.x;
    red[t] = s;
    __syncthreads();
    for (int st = 128; st > 0; st >>= 1) { if (t < st) red[t] += red[t + st]; __syncthreads(); }
    if (t == 0) ps[c * 64 + b] = red[0];
    __syncthreads();
    red[t] = ss;
    __syncthreads();
    for (int st = 128; st > 0; st >>= 1) { if (t < st) red[t] += red[t + st]; __syncthreads(); }
    if (t == 0) pss[c * 64 + b] = red[0];
}

// ---------------- host launch ----------------
extern "C" void kernel_launch(void* const* d_in, const int* in_sizes, int n_in,
                              void* d_out, int out_size) {
    const float* x     = (const float*)d_in[0];
    const float* Wc    = (const float*)d_in[1];
    const float* bn1g  = (const float*)d_in[2];
    const float* bn1b  = (const float*)d_in[3];
    const float* cqw   = (const float*)d_in[4];
    const float* cqb   = (const float*)d_in[5];
    const float* ckw   = (const float*)d_in[6];
    const float* ckb   = (const float*)d_in[7];
    const float* cvw   = (const float*)d_in[8];
    const float* cvb   = (const float*)d_in[9];
    const float* pqw   = (const float*)d_in[10];
    const float* pqb   = (const float*)d_in[11];
    const float* pkw   = (const float*)d_in[12];
    const float* pkb   = (const float*)d_in[13];
    const float* pvw   = (const float*)d_in[14];
    const float* pvb   = (const float*)d_in[15];
    const float* gamma1= (const float*)d_in[16];
    const float* gamma2= (const float*)d_in[17];
    const float* bn2g  = (const float*)d_in[18];
    const float* bn2b  = (const float*)d_in[19];
    const float* Wd    = (const float*)d_in[20];
    const float* bn3g  = (const float*)d_in[21];
    const float* bn3b  = (const float*)d_in[22];

    float* base = nullptr;
    cudaGetSymbolAddress((void**)&base, g_buf);
    float* t0    = base + OFF_T0;
    float* feat1 = base + OFF_FEAT1;
    float* vb    = base + OFF_VB;
    float* pvd   = base + OFF_PVD;
    float* sab   = base + OFF_SAB;
    float* scb   = base + OFF_SCB;
    float* bn2o  = base + OFF_BN2O;
    float* qb    = base + OFF_QB;
    float* kb    = base + OFF_KB;
    float* pqd   = base + OFF_PQD;
    float* pkd   = base + OFF_PKD;
    float* attn  = base + OFF_ATTN;
    float* ps    = base + OFF_PS;
    float* pss   = base + OFF_PSS;
    float* scale = base + OFF_SCALE;
    float* shift = base + OFF_SHIFT;

    dim3 cgrid(5, 5, Bv * Cv), cblk(16, 16);

    // stage 1: conv_c -> BN1 -> ReLU
    conv3x3_kernel<<<cgrid, cblk>>>(x, Wc, t0, ps, pss);
    bn_finalize<<<1, 64>>>(ps, pss, bn1g, bn1b, scale, shift, 50);
    bn_apply_kernel<<<3200, 256>>>(t0, feat1, scale, shift, 1);

    // projections
    conv2x2_kernel<<<Bv * Cv, 256>>>(feat1, cqw, cqb, qb);
    conv2x2_kernel<<<Bv * Cv, 256>>>(feat1, ckw, ckb, kb);
    conv1x1_kernel<64><<<dim3(Bv, 50), 128>>>(feat1, cvw, 0, cvb, vb);
    conv1x1_kernel<8><<<dim3(Bv, 50), 128>>>(feat1, pqw, 0, pqb, pqd);
    conv1x1_kernel<8><<<dim3(Bv, 50), 128>>>(feat1, pkw, 0, pkb, pkd);
    conv1x1_kernel<64><<<dim3(Bv, 50), 128>>>(feat1, pvw, 0, pvb, pvd);

    // CAM
    cam_kernel<<<Bv * Cv, 64>>>(qb, kb, attn);
    conv1x1_kernel<64><<<dim3(Bv, 50), 128>>>(vb, attn, 4096, nullptr, sab);

    // PAM (flash attention)
    pam_kernel<<<dim3(50, 2, Bv), 128>>>(pqd, pkd, pvd, scb);

    // combine + BN2 -> conv_d -> BN3 -> ReLU
    fsum_kernel<<<Bv * Cv, 256>>>(sab, scb, feat1, gamma1, gamma2, t0, ps, pss);
    bn_finalize<<<1, 64>>>(ps, pss, bn2g, bn2b, scale, shift, 2);
    bn_apply_kernel<<<3200, 256>>>(t0, bn2o, scale, shift, 0);
    conv3x3_kernel<<<cgrid, cblk>>>(bn2o, Wd, t0, ps, pss);
    bn_finalize<<<1, 64>>>(ps, pss, bn3g, bn3b, scale, shift, 50);
    bn_apply_kernel<<<3200, 256>>>(t0, (float*)d_out, scale, shift, 1);
}

// round 4
// speedup vs baseline: 1.3669x; 1.3669x over previous
#include <cuda_runtime.h>
#include <cuda_bf16.h>
#include <math.h>

#define Bv 2
#define Cv 64
#define Hv 80
#define Wv 80
#define Nv 6400
#define NQ 1600
#define NHWf 12800.0f
#define EPSV 1e-5f
#define L2E 1.44269504088896f

typedef unsigned long long ull;

// ---------------- f32x2 packed helpers ----------------
__device__ __forceinline__ ull pk2(float lo, float hi) {
    ull r; asm("mov.b64 %0,{%1,%2};" : "=l"(r) : "f"(lo), "f"(hi)); return r;
}
__device__ __forceinline__ void upk2(ull v, float& lo, float& hi) {
    asm("mov.b64 {%0,%1},%2;" : "=f"(lo), "=f"(hi) : "l"(v));
}
__device__ __forceinline__ ull fma2_(ull a, ull b, ull c) {
    ull d; asm("fma.rn.f32x2 %0,%1,%2,%3;" : "=l"(d) : "l"(a), "l"(b), "l"(c)); return d;
}
__device__ __forceinline__ ull mul2_(ull a, ull b) {
    ull d; asm("mul.rn.f32x2 %0,%1,%2;" : "=l"(d) : "l"(a), "l"(b)); return d;
}
__device__ __forceinline__ ull add2_(ull a, ull b) {
    ull d; asm("add.rn.f32x2 %0,%1,%2;" : "=l"(d) : "l"(a), "l"(b)); return d;
}

// ---------------- scratch ----------------
#define OFF_T0     0
#define OFF_FEAT1  (OFF_T0   + Bv*Cv*Nv)
#define OFF_VB     (OFF_FEAT1+ Bv*Cv*Nv)
#define OFF_PVD    (OFF_VB   + Bv*Cv*Nv)
#define OFF_SAB    (OFF_PVD  + Bv*Cv*Nv)
#define OFF_SCB    (OFF_SAB  + Bv*Cv*Nv)
#define OFF_QB     (OFF_SCB  + Bv*Cv*Nv)
#define OFF_KB     (OFF_QB   + Bv*Cv*NQ)
#define OFF_PQD    (OFF_KB   + Bv*Cv*NQ)
#define OFF_PKD    (OFF_PQD  + Bv*8*Nv)
#define OFF_ATTN   (OFF_PKD  + Bv*8*Nv)
#define OFF_PS     (OFF_ATTN + Bv*Cv*Cv)
#define OFF_PSS    (OFF_PS   + 64*64)
#define OFF_SCALE  (OFF_PSS  + 64*64)
#define OFF_SHIFT  (OFF_SCALE+ 64)
#define BUF_TOTAL  (OFF_SHIFT+ 64)

__device__ __align__(16) float g_buf[BUF_TOTAL];

// ---------------- conv3x3 (pad=1, no bias), 16 co per block, full-channel smem tile ----
// grid (5,5, B*4), block (16,16). Optional input-side affine (fused BN apply).
// dynamic smem: tile 64*324 floats + packed weight pairs 64*9*8 ull = 119808 B
template <int AFFINE>
__global__ void conv3x3_kernel(const float* __restrict__ in, const float* __restrict__ w,
                               const float* __restrict__ scale, const float* __restrict__ shift,
                               float* __restrict__ out) {
    extern __shared__ float sm[];
    float* tile = sm;                                   // 64*324
    ull* w2 = (ull*)(sm + 64 * 324);                    // [ci*9+tap][8] co-pairs
    __shared__ float aff[128];
    int bz = blockIdx.z;
    int b = bz >> 2, co0 = (bz & 3) * 16;
    int t = threadIdx.y * 16 + threadIdx.x;

    // weights transposed + co-paired: wflat[r*16+co] = w[(co0+co)*576 + r]
    float* wflat = (float*)w2;
    for (int i = t; i < 9216; i += 256) {
        int co = i & 15, r = i >> 4;
        wflat[r * 16 + co] = w[(co0 + co) * 576 + r];
    }
    if (AFFINE && t < 128) aff[t] = (t < 64) ? scale[t] : shift[t - 64];
    __syncthreads();

    int oy0 = blockIdx.y * 16, ox0 = blockIdx.x * 16;
    const float* inb = in + (long)b * Cv * Nv;
    for (int i = t; i < 64 * 324; i += 256) {
        int ci = i / 324;
        int pos = i - ci * 324;
        int r = pos / 18, c2 = pos - r * 18;
        int gy = oy0 + r - 1, gx = ox0 + c2 - 1;
        float v = 0.f;
        if (gy >= 0 && gy < Hv && gx >= 0 && gx < Wv) {
            v = inb[ci * Nv + gy * Wv + gx];
            if (AFFINE) v = v * aff[ci] + aff[64 + ci];
        }
        tile[i] = v;
    }
    __syncthreads();

    ull acc2[8];
#pragma unroll
    for (int c2 = 0; c2 < 8; c2++) acc2[c2] = pk2(0.f, 0.f);

    for (int ci = 0; ci < 64; ci++) {
        const float* tp = tile + ci * 324 + threadIdx.y * 18 + threadIdx.x;
        float x[9];
#pragma unroll
        for (int ky = 0; ky < 3; ky++)
#pragma unroll
            for (int kx = 0; kx < 3; kx++) x[ky * 3 + kx] = tp[ky * 18 + kx];
        const ull* wr = w2 + (long)ci * 72;
#pragma unroll
        for (int tap = 0; tap < 9; tap++) {
            ull xd = pk2(x[tap], x[tap]);
#pragma unroll
            for (int c2 = 0; c2 < 8; c2++)
                acc2[c2] = fma2_(xd, wr[tap * 8 + c2], acc2[c2]);
        }
    }
    long obase = ((long)b * 64 + co0) * Nv + (oy0 + threadIdx.y) * Wv + ox0 + threadIdx.x;
#pragma unroll
    for (int c2 = 0; c2 < 8; c2++) {
        float lo, hi;
        upk2(acc2[c2], lo, hi);
        out[obase + (long)(2 * c2) * Nv] = lo;
        out[obase + (long)(2 * c2 + 1) * Nv] = hi;
    }
}

// ---------------- per-channel stats (sum, sumsq) ----------------
// grid (B*C), block 256. slot = b (2 slots/channel)
__global__ void stats_kernel(const float* __restrict__ in, float* __restrict__ ps,
                             float* __restrict__ pss) {
    __shared__ float r1[256], r2[256];
    int bz = blockIdx.x;
    int b = bz >> 6, c = bz & 63;
    const float4* p4 = (const float4*)(in + (long)bz * Nv);
    float s = 0.f, ss = 0.f;
    for (int i = threadIdx.x; i < 1600; i += 256) {
        float4 v = p4[i];
        s += v.x + v.y + v.z + v.w;
        ss += v.x * v.x + v.y * v.y + v.z * v.z + v.w * v.w;
    }
    int t = threadIdx.x;
    r1[t] = s; r2[t] = ss;
    __syncthreads();
    for (int st = 128; st > 0; st >>= 1) {
        if (t < st) { r1[t] += r1[t + st]; r2[t] += r2[t + st]; }
        __syncthreads();
    }
    if (t == 0) { ps[c * 64 + b] = r1[0]; pss[c * 64 + b] = r2[0]; }
}

// ---------------- BN finalize ----------------
__global__ void bn_finalize(const float* __restrict__ ps, const float* __restrict__ pss,
                            const float* __restrict__ g, const float* __restrict__ bb,
                            float* __restrict__ scale, float* __restrict__ shift, int nslots) {
    int c = threadIdx.x;
    float s = 0.f, ss = 0.f;
    for (int i = 0; i < nslots; i++) { s += ps[c * 64 + i]; ss += pss[c * 64 + i]; }
    float m = s / NHWf;
    float var = ss / NHWf - m * m;
    float rs = rsqrtf(var + EPSV);
    float sc = g[c] * rs;
    scale[c] = sc;
    shift[c] = bb[c] - m * sc;
}

// ---------------- BN apply (float4, +optional relu) ----------------
// grid 800, block 256: 204800 float4 = 819200 floats
__global__ void bn_apply_kernel(const float4* __restrict__ in, float4* __restrict__ out,
                                const float* __restrict__ scale, const float* __restrict__ shift,
                                int relu) {
    int i = blockIdx.x * 256 + threadIdx.x;
    int c = (i / 1600) & 63;
    float sc = scale[c], sh = shift[c];
    float4 v = in[i];
    v.x = v.x * sc + sh; v.y = v.y * sc + sh; v.z = v.z * sc + sh; v.w = v.w * sc + sh;
    if (relu) {
        v.x = fmaxf(v.x, 0.f); v.y = fmaxf(v.y, 0.f);
        v.z = fmaxf(v.z, 0.f); v.w = fmaxf(v.w, 0.f);
    }
    out[i] = v;
}

// ---------------- fused conv2x2 stride2 (q and k) ----------------
// grid (13, 8, B): y = conv*4 + cogrp(16 co). block 128 (one output pixel each).
__global__ void convqk_kernel(const float* __restrict__ in,
                              const float* __restrict__ wq, const float* __restrict__ bq,
                              const float* __restrict__ wk, const float* __restrict__ bk,
                              float* __restrict__ outq, float* __restrict__ outk) {
    __shared__ __align__(16) float wsm[4096];  // [ci*4+tap][16co]
    int conv = blockIdx.y >> 2;
    int co0 = (blockIdx.y & 3) * 16;
    int b = blockIdx.z;
    const float* w = conv ? wk : wq;
    const float* bias = conv ? bk : bq;
    float* out = conv ? outk : outq;

    for (int i = threadIdx.x; i < 4096; i += 128) {
        int co = i & 15, r = i >> 4;  // r = ci*4+tap
        wsm[r * 16 + co] = w[(co0 + co) * 256 + r];
    }
    __syncthreads();

    int p = blockIdx.x * 128 + threadIdx.x;
    if (p >= NQ) return;
    int oy = p / 40, ox = p % 40;
    const float* inb = in + (long)b * Cv * Nv + (2 * oy) * Wv + 2 * ox;

    ull acc2[8];
    const ull* w2 = (const ull*)wsm;
#pragma unroll
    for (int c2 = 0; c2 < 8; c2++) acc2[c2] = pk2(bias[co0 + 2 * c2], bias[co0 + 2 * c2 + 1]);

#pragma unroll 4
    for (int ci = 0; ci < 64; ci++) {
        float2 a = *(const float2*)(inb + ci * Nv);
        float2 bb2 = *(const float2*)(inb + ci * Nv + Wv);
        ull x0 = pk2(a.x, a.x), x1 = pk2(a.y, a.y);
        ull x2 = pk2(bb2.x, bb2.x), x3 = pk2(bb2.y, bb2.y);
        const ull* wr = w2 + ci * 32;  // 4 taps * 8 pairs
#pragma unroll
        for (int c2 = 0; c2 < 8; c2++) {
            ull a2 = fma2_(x0, wr[c2], acc2[c2]);
            a2 = fma2_(x1, wr[8 + c2], a2);
            a2 = fma2_(x2, wr[16 + c2], a2);
            acc2[c2] = fma2_(x3, wr[24 + c2], a2);
        }
    }
    long obase = ((long)b * 64 + co0) * NQ + p;
#pragma unroll
    for (int c2 = 0; c2 < 8; c2++) {
        float lo, hi;
        upk2(acc2[c2], lo, hi);
        out[obase + (long)(2 * c2) * NQ] = lo;
        out[obase + (long)(2 * c2 + 1) * NQ] = hi;
    }
}

// ---------------- conv1x1 (CO outputs, 64 inputs); weights optionally per-batch -------
// grid (B, 50), block 128. weights transposed in smem: wsm[ci*CO + co]
template <int CO>
__global__ void conv1x1_kernel(const float* __restrict__ in, const float* __restrict__ w,
                               int wstride, const float* __restrict__ bias,
                               float* __restrict__ out) {
    __shared__ __align__(16) float wsm[CO * 64];
    int b = blockIdx.x;
    int n = blockIdx.y * 128 + threadIdx.x;
    const float* wb = w + (long)b * wstride;
    for (int i = threadIdx.x; i < CO * 64; i += 128) {
        int co = i >> 6, ci = i & 63;
        wsm[ci * CO + co] = wb[i];
    }
    __syncthreads();
    float acc[CO];
#pragma unroll
    for (int co = 0; co < CO; co++) acc[co] = bias ? bias[co] : 0.f;
    const float* inb = in + (long)b * 64 * Nv + n;
    const float4* wsm4 = (const float4*)wsm;
#pragma unroll 4
    for (int ci = 0; ci < 64; ci++) {
        float xv = inb[ci * Nv];
#pragma unroll
        for (int c4 = 0; c4 < CO / 4; c4++) {
            float4 w4 = wsm4[ci * (CO / 4) + c4];
            acc[c4 * 4 + 0] += w4.x * xv;
            acc[c4 * 4 + 1] += w4.y * xv;
            acc[c4 * 4 + 2] += w4.z * xv;
            acc[c4 * 4 + 3] += w4.w * xv;
        }
    }
    float* ob = out + (long)b * CO * Nv + n;
#pragma unroll
    for (int co = 0; co < CO; co++) ob[co * Nv] = acc[co];
}

// ---------------- CAM energy + softmax ----------------
__global__ void cam_kernel(const float* __restrict__ q, const float* __restrict__ k,
                           float* __restrict__ attn) {
    __shared__ __align__(16) float qsm[NQ];
    __shared__ float er[64];
    __shared__ float pe[64];
    int b = blockIdx.x >> 6, c = blockIdx.x & 63;
    const float* qr = q + (long)(b * 64 + c) * NQ;
    for (int i = threadIdx.x; i < NQ; i += 64) qsm[i] = qr[i];
    __syncthreads();
    int d = threadIdx.x;
    const float4* kr = (const float4*)(k + (long)(b * 64 + d) * NQ);
    const float4* q4 = (const float4*)qsm;
    float s = 0.f;
#pragma unroll 4
    for (int i = 0; i < NQ / 4; i++) {
        float4 kv = kr[i];
        float4 qv = q4[i];
        s += qv.x * kv.x + qv.y * kv.y + qv.z * kv.z + qv.w * kv.w;
    }
    er[d] = s;
    __syncthreads();
    float mn = er[0];
    for (int i = 1; i < 64; i++) mn = fminf(mn, er[i]);
    float p = __expf(mn - s);
    pe[d] = p;
    __syncthreads();
    float sum = 0.f;
    for (int i = 0; i < 64; i++) sum += pe[i];
    attn[(long)(b * 64 + c) * 64 + d] = p / sum;
}

// ---------------- PAM: flash attention, d=8, dv=64, f32x2 packed ----------------
// grid (100, 2, B): x = query tile (64 q), y = channel half (32), z = batch
__global__ void __launch_bounds__(64) pam_kernel(const float* __restrict__ pq,
                                                 const float* __restrict__ pk,
                                                 const float* __restrict__ pv,
                                                 float* __restrict__ sc) {
    __shared__ __align__(16) float ks[8 * 32];
    __shared__ __align__(16) float vs[32 * 32];
    int b = blockIdx.z, ch0 = blockIdx.y * 32;
    int n = blockIdx.x * 64 + threadIdx.x;
    const float* pqb = pq + (long)b * 8 * Nv;
    const float* pkb = pk + (long)b * 8 * Nv;
    const float* pvb = pv + (long)(b * 64 + ch0) * Nv;

    ull q2[8];
#pragma unroll
    for (int e = 0; e < 8; e++) {
        float qv = pqb[e * Nv + n] * L2E;  // exp2 domain
        q2[e] = pk2(qv, qv);
    }
    ull o2[32];
#pragma unroll
    for (int c = 0; c < 32; c++) o2[c] = pk2(0.f, 0.f);
    ull li2 = pk2(0.f, 0.f);
    float mi = -1e30f;

    for (int m0 = 0; m0 < Nv; m0 += 32) {
        __syncthreads();
        for (int i = threadIdx.x; i < 256; i += 64)
            ks[i] = pkb[(i >> 5) * Nv + m0 + (i & 31)];
        for (int i = threadIdx.x; i < 1024; i += 64)
            vs[i] = pvb[(long)(i >> 5) * Nv + m0 + (i & 31)];
        __syncthreads();

        // QK: s2 pairs over adjacent j
        ull s2[16];
        {
            const ulonglong2* k2p = (const ulonglong2*)ks;
#pragma unroll
            for (int j4 = 0; j4 < 8; j4++) {
                ulonglong2 kk = k2p[j4];
                s2[2 * j4] = mul2_(q2[0], kk.x);
                s2[2 * j4 + 1] = mul2_(q2[0], kk.y);
            }
        }
#pragma unroll
        for (int e = 1; e < 8; e++) {
            const ulonglong2* k2p = (const ulonglong2*)(ks + e * 32);
#pragma unroll
            for (int j4 = 0; j4 < 8; j4++) {
                ulonglong2 kk = k2p[j4];
                s2[2 * j4] = fma2_(q2[e], kk.x, s2[2 * j4]);
                s2[2 * j4 + 1] = fma2_(q2[e], kk.y, s2[2 * j4 + 1]);
            }
        }
        float s[32];
#pragma unroll
        for (int j2 = 0; j2 < 16; j2++) upk2(s2[j2], s[2 * j2], s[2 * j2 + 1]);
        float tmax = s[0];
#pragma unroll
        for (int j = 1; j < 32; j++) tmax = fmaxf(tmax, s[j]);
        float mnew = fmaxf(mi, tmax);
        float corr = exp2f(mi - mnew);
        ull corr2 = pk2(corr, corr);
        ull p2[16];
#pragma unroll
        for (int j2 = 0; j2 < 16; j2++)
            p2[j2] = pk2(exp2f(s[2 * j2] - mnew), exp2f(s[2 * j2 + 1] - mnew));
        li2 = mul2_(li2, corr2);
#pragma unroll
        for (int j2 = 0; j2 < 16; j2++) li2 = add2_(li2, p2[j2]);
#pragma unroll
        for (int c = 0; c < 32; c++) o2[c] = mul2_(o2[c], corr2);
#pragma unroll
        for (int c = 0; c < 32; c++) {
            const ulonglong2* vr = (const ulonglong2*)(vs + c * 32);
            ull acc = o2[c];
#pragma unroll
            for (int j4 = 0; j4 < 8; j4++) {
                ulonglong2 vv = vr[j4];
                acc = fma2_(p2[2 * j4], vv.x, acc);
                acc = fma2_(p2[2 * j4 + 1], vv.y, acc);
            }
            o2[c] = acc;
        }
        mi = mnew;
    }
    float llo, lhi;
    upk2(li2, llo, lhi);
    float inv = 1.f / (llo + lhi);
    float* scp = sc + (long)(b * 64 + ch0) * Nv + n;
#pragma unroll
    for (int c = 0; c < 32; c++) {
        float lo, hi;
        upk2(o2[c], lo, hi);
        scp[(long)c * Nv] = (lo + hi) * inv;
    }
}

// ---------------- feat_sum + BN2 partial stats ----------------
__global__ void fsum_kernel(const float* __restrict__ sa, const float* __restrict__ sc,
                            const float* __restrict__ f1, const float* __restrict__ gamma1,
                            const float* __restrict__ gamma2, float* __restrict__ out,
                            float* __restrict__ ps, float* __restrict__ pss) {
    __shared__ float r1[256], r2[256];
    int bz = blockIdx.x;
    int b = bz >> 6, c = bz & 63;
    float g1 = gamma1[0], g2 = gamma2[0];
    long base = (long)bz * Nv;
    const float4* sa4 = (const float4*)(sa + base);
    const float4* sc4 = (const float4*)(sc + base);
    const float4* f4 = (const float4*)(f1 + base);
    float4* o4 = (float4*)(out + base);
    float s = 0.f, ss = 0.f;
    for (int i = threadIdx.x; i < 1600; i += 256) {
        float4 a = sa4[i], bb = sc4[i], f = f4[i];
        float4 v;
        v.x = g1 * a.x + g2 * bb.x + f.x;
        v.y = g1 * a.y + g2 * bb.y + f.y;
        v.z = g1 * a.z + g2 * bb.z + f.z;
        v.w = g1 * a.w + g2 * bb.w + f.w;
        o4[i] = v;
        s += v.x + v.y + v.z + v.w;
        ss += v.x * v.x + v.y * v.y + v.z * v.z + v.w * v.w;
    }
    int t = threadIdx.x;
    r1[t] = s; r2[t] = ss;
    __syncthreads();
    for (int st = 128; st > 0; st >>= 1) {
        if (t < st) { r1[t] += r1[t + st]; r2[t] += r2[t + st]; }
        __syncthreads();
    }
    if (t == 0) { ps[c * 64 + b] = r1[0]; pss[c * 64 + b] = r2[0]; }
}

// ---------------- host launch ----------------
extern "C" void kernel_launch(void* const* d_in, const int* in_sizes, int n_in,
                              void* d_out, int out_size) {
    const float* x     = (const float*)d_in[0];
    const float* Wc    = (const float*)d_in[1];
    const float* bn1g  = (const float*)d_in[2];
    const float* bn1b  = (const float*)d_in[3];
    const float* cqw   = (const float*)d_in[4];
    const float* cqb   = (const float*)d_in[5];
    const float* ckw   = (const float*)d_in[6];
    const float* ckb   = (const float*)d_in[7];
    const float* cvw   = (const float*)d_in[8];
    const float* cvb   = (const float*)d_in[9];
    const float* pqw   = (const float*)d_in[10];
    const float* pqb   = (const float*)d_in[11];
    const float* pkw   = (const float*)d_in[12];
    const float* pkb   = (const float*)d_in[13];
    const float* pvw   = (const float*)d_in[14];
    const float* pvb   = (const float*)d_in[15];
    const float* gamma1= (const float*)d_in[16];
    const float* gamma2= (const float*)d_in[17];
    const float* bn2g  = (const float*)d_in[18];
    const float* bn2b  = (const float*)d_in[19];
    const float* Wd    = (const float*)d_in[20];
    const float* bn3g  = (const float*)d_in[21];
    const float* bn3b  = (const float*)d_in[22];

    float* base = nullptr;
    cudaGetSymbolAddress((void**)&base, g_buf);
    float* t0    = base + OFF_T0;
    float* feat1 = base + OFF_FEAT1;
    float* vb    = base + OFF_VB;
    float* pvd   = base + OFF_PVD;
    float* sab   = base + OFF_SAB;
    float* scb   = base + OFF_SCB;
    float* qb    = base + OFF_QB;
    float* kb    = base + OFF_KB;
    float* pqd   = base + OFF_PQD;
    float* pkd   = base + OFF_PKD;
    float* attn  = base + OFF_ATTN;
    float* ps    = base + OFF_PS;
    float* pss   = base + OFF_PSS;
    float* scale = base + OFF_SCALE;
    float* shift = base + OFF_SHIFT;

    const int C3SMEM = 64 * 324 * 4 + 64 * 9 * 8 * 8;  // 119808
    cudaFuncSetAttribute(conv3x3_kernel<0>, cudaFuncAttributeMaxDynamicSharedMemorySize, C3SMEM);
    cudaFuncSetAttribute(conv3x3_kernel<1>, cudaFuncAttributeMaxDynamicSharedMemorySize, C3SMEM);

    dim3 cgrid(5, 5, Bv * 4), cblk(16, 16);

    // stage 1: conv_c -> BN1 -> ReLU
    conv3x3_kernel<0><<<cgrid, cblk, C3SMEM>>>(x, Wc, nullptr, nullptr, t0);
    stats_kernel<<<Bv * Cv, 256>>>(t0, ps, pss);
    bn_finalize<<<1, 64>>>(ps, pss, bn1g, bn1b, scale, shift, 2);
    bn_apply_kernel<<<800, 256>>>((const float4*)t0, (float4*)feat1, scale, shift, 1);

    // projections
    convqk_kernel<<<dim3(13, 8, Bv), 128>>>(feat1, cqw, cqb, ckw, ckb, qb, kb);
    conv1x1_kernel<64><<<dim3(Bv, 50), 128>>>(feat1, cvw, 0, cvb, vb);
    conv1x1_kernel<8><<<dim3(Bv, 50), 128>>>(feat1, pqw, 0, pqb, pqd);
    conv1x1_kernel<8><<<dim3(Bv, 50), 128>>>(feat1, pkw, 0, pkb, pkd);
    conv1x1_kernel<64><<<dim3(Bv, 50), 128>>>(feat1, pvw, 0, pvb, pvd);

    // CAM
    cam_kernel<<<Bv * Cv, 64>>>(qb, kb, attn);
    conv1x1_kernel<64><<<dim3(Bv, 50), 128>>>(vb, attn, 4096, nullptr, sab);

    // PAM (flash attention, f32x2)
    pam_kernel<<<dim3(100, 2, Bv), 64>>>(pqd, pkd, pvd, scb);

    // combine + BN2 (folded into conv_d input) -> conv_d -> BN3 -> ReLU
    fsum_kernel<<<Bv * Cv, 256>>>(sab, scb, feat1, gamma1, gamma2, t0, ps, pss);
    bn_finalize<<<1, 64>>>(ps, pss, bn2g, bn2b, scale, shift, 2);
    conv3x3_kernel<1><<<cgrid, cblk, C3SMEM>>>(t0, Wd, scale, shift, feat1);
    stats_kernel<<<Bv * Cv, 256>>>(feat1, ps, pss);
    bn_finalize<<<1, 64>>>(ps, pss, bn3g, bn3b, scale, shift, 2);
    bn_apply_kernel<<<800, 256>>>((const float4*)feat1, (float4*)d_out, scale, shift, 1);
}

// round 5
// speedup vs baseline: 1.4930x; 1.0922x over previous
#include <cuda_runtime.h>
#include <cuda_bf16.h>
#include <math.h>

#define Bv 2
#define Cv 64
#define Hv 80
#define Wv 80
#define Nv 6400
#define NQ 1600
#define NHWf 12800.0f
#define EPSV 1e-5f
#define L2E 1.44269504088896f

typedef unsigned long long ull;

// ---------------- f32x2 packed helpers ----------------
__device__ __forceinline__ ull pk2(float lo, float hi) {
    ull r; asm("mov.b64 %0,{%1,%2};" : "=l"(r) : "f"(lo), "f"(hi)); return r;
}
__device__ __forceinline__ void upk2(ull v, float& lo, float& hi) {
    asm("mov.b64 {%0,%1},%2;" : "=f"(lo), "=f"(hi) : "l"(v));
}
__device__ __forceinline__ ull fma2_(ull a, ull b, ull c) {
    ull d; asm("fma.rn.f32x2 %0,%1,%2,%3;" : "=l"(d) : "l"(a), "l"(b), "l"(c)); return d;
}
__device__ __forceinline__ ull mul2_(ull a, ull b) {
    ull d; asm("mul.rn.f32x2 %0,%1,%2;" : "=l"(d) : "l"(a), "l"(b)); return d;
}
__device__ __forceinline__ ull add2_(ull a, ull b) {
    ull d; asm("add.rn.f32x2 %0,%1,%2;" : "=l"(d) : "l"(a), "l"(b)); return d;
}
__device__ __forceinline__ float ex2_(float x) {
    float y; asm("ex2.approx.ftz.f32 %0,%1;" : "=f"(y) : "f"(x)); return y;
}

// ---------------- scratch ----------------
#define OFF_T0     0
#define OFF_FEAT1  (OFF_T0   + Bv*Cv*Nv)
#define OFF_VB     (OFF_FEAT1+ Bv*Cv*Nv)
#define OFF_PVD    (OFF_VB   + Bv*Cv*Nv)
#define OFF_SAB    (OFF_PVD  + Bv*Cv*Nv)
#define OFF_SCB    (OFF_SAB  + Bv*Cv*Nv)
#define OFF_QB     (OFF_SCB  + Bv*Cv*Nv)
#define OFF_KB     (OFF_QB   + Bv*Cv*NQ)
#define OFF_PQD    (OFF_KB   + Bv*Cv*NQ)
#define OFF_PKD    (OFF_PQD  + Bv*8*Nv)
#define OFF_ATTN   (OFF_PKD  + Bv*8*Nv)
#define OFF_PS     (OFF_ATTN + Bv*Cv*Cv)
#define OFF_PSS    (OFF_PS   + 64*64)
#define OFF_SCALE  (OFF_PSS  + 64*64)
#define OFF_SHIFT  (OFF_SCALE+ 64)
#define BUF_TOTAL  (OFF_SHIFT+ 64)

__device__ __align__(16) float g_buf[BUF_TOTAL];

// ---------------- conv3x3 (pad=1, no bias), 16 co per block, 2x32-channel smem chunks --
// grid (5,5, B*4), block (16,16). Optional input-side affine (fused BN apply).
// dynamic smem: tile 32*324 floats + packed weight pairs 64*9*8 ull = 78336 B (2 blocks/SM)
template <int AFFINE>
__global__ void conv3x3_kernel(const float* __restrict__ in, const float* __restrict__ w,
                               const float* __restrict__ scale, const float* __restrict__ shift,
                               float* __restrict__ out) {
    extern __shared__ float sm[];
    float* tile = sm;                                   // 32*324
    ull* w2 = (ull*)(sm + 32 * 324);                    // [ci*9+tap][8] co-pairs (all 64 ci)
    __shared__ float aff[128];
    int bz = blockIdx.z;
    int b = bz >> 2, co0 = (bz & 3) * 16;
    int t = threadIdx.y * 16 + threadIdx.x;

    // weights transposed + co-paired: wflat[r*16+co] = w[(co0+co)*576 + r]
    float* wflat = (float*)w2;
    for (int i = t; i < 9216; i += 256) {
        int co = i & 15, r = i >> 4;
        wflat[r * 16 + co] = w[(co0 + co) * 576 + r];
    }
    if (AFFINE && t < 128) aff[t] = (t < 64) ? scale[t] : shift[t - 64];

    int oy0 = blockIdx.y * 16, ox0 = blockIdx.x * 16;
    const float* inb = in + (long)b * Cv * Nv;

    ull acc2[8];
#pragma unroll
    for (int c2 = 0; c2 < 8; c2++) acc2[c2] = pk2(0.f, 0.f);

    for (int chunk = 0; chunk < 2; chunk++) {
        int cbase = chunk * 32;
        __syncthreads();
        for (int i = t; i < 32 * 324; i += 256) {
            int ci = i / 324;
            int pos = i - ci * 324;
            int r = pos / 18, c2 = pos - r * 18;
            int gy = oy0 + r - 1, gx = ox0 + c2 - 1;
            float v = 0.f;
            if (gy >= 0 && gy < Hv && gx >= 0 && gx < Wv) {
                v = inb[(cbase + ci) * Nv + gy * Wv + gx];
                if (AFFINE) v = v * aff[cbase + ci] + aff[64 + cbase + ci];
            }
            tile[i] = v;
        }
        __syncthreads();

        for (int ci = 0; ci < 32; ci++) {
            const float* tp = tile + ci * 324 + threadIdx.y * 18 + threadIdx.x;
            float x[9];
#pragma unroll
            for (int ky = 0; ky < 3; ky++)
#pragma unroll
                for (int kx = 0; kx < 3; kx++) x[ky * 3 + kx] = tp[ky * 18 + kx];
            const ull* wr = w2 + (long)(cbase + ci) * 72;
#pragma unroll
            for (int tap = 0; tap < 9; tap++) {
                ull xd = pk2(x[tap], x[tap]);
#pragma unroll
                for (int c2 = 0; c2 < 8; c2++)
                    acc2[c2] = fma2_(xd, wr[tap * 8 + c2], acc2[c2]);
            }
        }
    }
    long obase = ((long)b * 64 + co0) * Nv + (oy0 + threadIdx.y) * Wv + ox0 + threadIdx.x;
#pragma unroll
    for (int c2 = 0; c2 < 8; c2++) {
        float lo, hi;
        upk2(acc2[c2], lo, hi);
        out[obase + (long)(2 * c2) * Nv] = lo;
        out[obase + (long)(2 * c2 + 1) * Nv] = hi;
    }
}

// ---------------- per-channel stats (sum, sumsq) ----------------
__global__ void stats_kernel(const float* __restrict__ in, float* __restrict__ ps,
                             float* __restrict__ pss) {
    __shared__ float r1[256], r2[256];
    int bz = blockIdx.x;
    int b = bz >> 6, c = bz & 63;
    const float4* p4 = (const float4*)(in + (long)bz * Nv);
    float s = 0.f, ss = 0.f;
    for (int i = threadIdx.x; i < 1600; i += 256) {
        float4 v = p4[i];
        s += v.x + v.y + v.z + v.w;
        ss += v.x * v.x + v.y * v.y + v.z * v.z + v.w * v.w;
    }
    int t = threadIdx.x;
    r1[t] = s; r2[t] = ss;
    __syncthreads();
    for (int st = 128; st > 0; st >>= 1) {
        if (t < st) { r1[t] += r1[t + st]; r2[t] += r2[t + st]; }
        __syncthreads();
    }
    if (t == 0) { ps[c * 64 + b] = r1[0]; pss[c * 64 + b] = r2[0]; }
}

// ---------------- BN finalize ----------------
__global__ void bn_finalize(const float* __restrict__ ps, const float* __restrict__ pss,
                            const float* __restrict__ g, const float* __restrict__ bb,
                            float* __restrict__ scale, float* __restrict__ shift, int nslots) {
    int c = threadIdx.x;
    float s = 0.f, ss = 0.f;
    for (int i = 0; i < nslots; i++) { s += ps[c * 64 + i]; ss += pss[c * 64 + i]; }
    float m = s / NHWf;
    float var = ss / NHWf - m * m;
    float rs = rsqrtf(var + EPSV);
    float sc = g[c] * rs;
    scale[c] = sc;
    shift[c] = bb[c] - m * sc;
}

// ---------------- BN apply (float4, +optional relu) ----------------
// grid 800, block 256: 204800 float4 = 819200 floats
__global__ void bn_apply_kernel(const float4* __restrict__ in, float4* __restrict__ out,
                                const float* __restrict__ scale, const float* __restrict__ shift,
                                int relu) {
    int i = blockIdx.x * 256 + threadIdx.x;
    int c = (i / 1600) & 63;
    float sc = scale[c], sh = shift[c];
    float4 v = in[i];
    v.x = v.x * sc + sh; v.y = v.y * sc + sh; v.z = v.z * sc + sh; v.w = v.w * sc + sh;
    if (relu) {
        v.x = fmaxf(v.x, 0.f); v.y = fmaxf(v.y, 0.f);
        v.z = fmaxf(v.z, 0.f); v.w = fmaxf(v.w, 0.f);
    }
    out[i] = v;
}

// ---------------- fused conv2x2 stride2 (q and k) ----------------
// grid (13, 8, B): y = conv*4 + cogrp(16 co). block 128 (one output pixel each).
__global__ void convqk_kernel(const float* __restrict__ in,
                              const float* __restrict__ wq, const float* __restrict__ bq,
                              const float* __restrict__ wk, const float* __restrict__ bk,
                              float* __restrict__ outq, float* __restrict__ outk) {
    __shared__ __align__(16) float wsm[4096];  // [ci*4+tap][16co]
    int conv = blockIdx.y >> 2;
    int co0 = (blockIdx.y & 3) * 16;
    int b = blockIdx.z;
    const float* w = conv ? wk : wq;
    const float* bias = conv ? bk : bq;
    float* out = conv ? outk : outq;

    for (int i = threadIdx.x; i < 4096; i += 128) {
        int co = i & 15, r = i >> 4;  // r = ci*4+tap
        wsm[r * 16 + co] = w[(co0 + co) * 256 + r];
    }
    __syncthreads();

    int p = blockIdx.x * 128 + threadIdx.x;
    if (p >= NQ) return;
    int oy = p / 40, ox = p % 40;
    const float* inb = in + (long)b * Cv * Nv + (2 * oy) * Wv + 2 * ox;

    ull acc2[8];
    const ull* w2 = (const ull*)wsm;
#pragma unroll
    for (int c2 = 0; c2 < 8; c2++) acc2[c2] = pk2(bias[co0 + 2 * c2], bias[co0 + 2 * c2 + 1]);

#pragma unroll 4
    for (int ci = 0; ci < 64; ci++) {
        float2 a = *(const float2*)(inb + ci * Nv);
        float2 bb2 = *(const float2*)(inb + ci * Nv + Wv);
        ull x0 = pk2(a.x, a.x), x1 = pk2(a.y, a.y);
        ull x2 = pk2(bb2.x, bb2.x), x3 = pk2(bb2.y, bb2.y);
        const ull* wr = w2 + ci * 32;  // 4 taps * 8 pairs
#pragma unroll
        for (int c2 = 0; c2 < 8; c2++) {
            ull a2 = fma2_(x0, wr[c2], acc2[c2]);
            a2 = fma2_(x1, wr[8 + c2], a2);
            a2 = fma2_(x2, wr[16 + c2], a2);
            acc2[c2] = fma2_(x3, wr[24 + c2], a2);
        }
    }
    long obase = ((long)b * 64 + co0) * NQ + p;
#pragma unroll
    for (int c2 = 0; c2 < 8; c2++) {
        float lo, hi;
        upk2(acc2[c2], lo, hi);
        out[obase + (long)(2 * c2) * NQ] = lo;
        out[obase + (long)(2 * c2 + 1) * NQ] = hi;
    }
}

// ---------------- conv1x1 (CO outputs, 64 inputs); weights optionally per-batch -------
template <int CO>
__global__ void conv1x1_kernel(const float* __restrict__ in, const float* __restrict__ w,
                               int wstride, const float* __restrict__ bias,
                               float* __restrict__ out) {
    __shared__ __align__(16) float wsm[CO * 64];
    int b = blockIdx.x;
    int n = blockIdx.y * 128 + threadIdx.x;
    const float* wb = w + (long)b * wstride;
    for (int i = threadIdx.x; i < CO * 64; i += 128) {
        int co = i >> 6, ci = i & 63;
        wsm[ci * CO + co] = wb[i];
    }
    __syncthreads();
    float acc[CO];
#pragma unroll
    for (int co = 0; co < CO; co++) acc[co] = bias ? bias[co] : 0.f;
    const float* inb = in + (long)b * 64 * Nv + n;
    const float4* wsm4 = (const float4*)wsm;
#pragma unroll 4
    for (int ci = 0; ci < 64; ci++) {
        float xv = inb[ci * Nv];
#pragma unroll
        for (int c4 = 0; c4 < CO / 4; c4++) {
            float4 w4 = wsm4[ci * (CO / 4) + c4];
            acc[c4 * 4 + 0] += w4.x * xv;
            acc[c4 * 4 + 1] += w4.y * xv;
            acc[c4 * 4 + 2] += w4.z * xv;
            acc[c4 * 4 + 3] += w4.w * xv;
        }
    }
    float* ob = out + (long)b * CO * Nv + n;
#pragma unroll
    for (int co = 0; co < CO; co++) ob[co * Nv] = acc[co];
}

// ---------------- CAM energy + softmax ----------------
__global__ void cam_kernel(const float* __restrict__ q, const float* __restrict__ k,
                           float* __restrict__ attn) {
    __shared__ __align__(16) float qsm[NQ];
    __shared__ float er[64];
    __shared__ float pe[64];
    int b = blockIdx.x >> 6, c = blockIdx.x & 63;
    const float* qr = q + (long)(b * 64 + c) * NQ;
    for (int i = threadIdx.x; i < NQ; i += 64) qsm[i] = qr[i];
    __syncthreads();
    int d = threadIdx.x;
    const float4* kr = (const float4*)(k + (long)(b * 64 + d) * NQ);
    const float4* q4 = (const float4*)qsm;
    float s = 0.f;
#pragma unroll 4
    for (int i = 0; i < NQ / 4; i++) {
        float4 kv = kr[i];
        float4 qv = q4[i];
        s += qv.x * kv.x + qv.y * kv.y + qv.z * kv.z + qv.w * kv.w;
    }
    er[d] = s;
    __syncthreads();
    float mn = er[0];
    for (int i = 1; i < 64; i++) mn = fminf(mn, er[i]);
    float p = __expf(mn - s);
    pe[d] = p;
    __syncthreads();
    float sum = 0.f;
    for (int i = 0; i < 64; i++) sum += pe[i];
    attn[(long)(b * 64 + c) * 64 + d] = p / sum;
}

// ---------------- PAM: flash attention, d=8, dv=64, f32x2 packed ----------------
// grid (50, 2, B): x = query tile (128 q), y = channel half (32), z = batch. 128 thr.
__global__ void __launch_bounds__(128) pam_kernel(const float* __restrict__ pq,
                                                  const float* __restrict__ pk,
                                                  const float* __restrict__ pv,
                                                  float* __restrict__ sc) {
    __shared__ __align__(16) float ks[8 * 32];
    __shared__ __align__(16) float vs[32 * 32];
    int b = blockIdx.z, ch0 = blockIdx.y * 32;
    int n = blockIdx.x * 128 + threadIdx.x;
    const float* pqb = pq + (long)b * 8 * Nv;
    const float* pkb = pk + (long)b * 8 * Nv;
    const float* pvb = pv + (long)(b * 64 + ch0) * Nv;

    ull q2[8];
#pragma unroll
    for (int e = 0; e < 8; e++) {
        float qv = pqb[e * Nv + n] * L2E;  // exp2 domain
        q2[e] = pk2(qv, qv);
    }
    ull o2[32];
#pragma unroll
    for (int c = 0; c < 32; c++) o2[c] = pk2(0.f, 0.f);
    ull li2 = pk2(0.f, 0.f);
    float mi = -1e30f;

    for (int m0 = 0; m0 < Nv; m0 += 32) {
        __syncthreads();
        for (int i = threadIdx.x; i < 256; i += 128)
            ks[i] = pkb[(i >> 5) * Nv + m0 + (i & 31)];
        for (int i = threadIdx.x; i < 1024; i += 128)
            vs[i] = pvb[(long)(i >> 5) * Nv + m0 + (i & 31)];
        __syncthreads();

        // QK: s2 pairs over adjacent j
        ull s2[16];
        {
            const ulonglong2* k2p = (const ulonglong2*)ks;
#pragma unroll
            for (int j4 = 0; j4 < 8; j4++) {
                ulonglong2 kk = k2p[j4];
                s2[2 * j4] = mul2_(q2[0], kk.x);
                s2[2 * j4 + 1] = mul2_(q2[0], kk.y);
            }
        }
#pragma unroll
        for (int e = 1; e < 8; e++) {
            const ulonglong2* k2p = (const ulonglong2*)(ks + e * 32);
#pragma unroll
            for (int j4 = 0; j4 < 8; j4++) {
                ulonglong2 kk = k2p[j4];
                s2[2 * j4] = fma2_(q2[e], kk.x, s2[2 * j4]);
                s2[2 * j4 + 1] = fma2_(q2[e], kk.y, s2[2 * j4 + 1]);
            }
        }
        float s[32];
#pragma unroll
        for (int j2 = 0; j2 < 16; j2++) upk2(s2[j2], s[2 * j2], s[2 * j2 + 1]);
        float tmax = s[0];
#pragma unroll
        for (int j = 1; j < 32; j++) tmax = fmaxf(tmax, s[j]);
        float mnew = fmaxf(mi, tmax);
        float corr = ex2_(mi - mnew);
        ull corr2 = pk2(corr, corr);
        ull p2[16];
#pragma unroll
        for (int j2 = 0; j2 < 16; j2++)
            p2[j2] = pk2(ex2_(s[2 * j2] - mnew), ex2_(s[2 * j2 + 1] - mnew));
        li2 = mul2_(li2, corr2);
#pragma unroll
        for (int j2 = 0; j2 < 16; j2++) li2 = add2_(li2, p2[j2]);
#pragma unroll
        for (int c = 0; c < 32; c++) o2[c] = mul2_(o2[c], corr2);
#pragma unroll
        for (int c = 0; c < 32; c++) {
            const ulonglong2* vr = (const ulonglong2*)(vs + c * 32);
            ull acc = o2[c];
#pragma unroll
            for (int j4 = 0; j4 < 8; j4++) {
                ulonglong2 vv = vr[j4];
                acc = fma2_(p2[2 * j4], vv.x, acc);
                acc = fma2_(p2[2 * j4 + 1], vv.y, acc);
            }
            o2[c] = acc;
        }
        mi = mnew;
    }
    float llo, lhi;
    upk2(li2, llo, lhi);
    float inv = 1.f / (llo + lhi);
    float* scp = sc + (long)(b * 64 + ch0) * Nv + n;
#pragma unroll
    for (int c = 0; c < 32; c++) {
        float lo, hi;
        upk2(o2[c], lo, hi);
        scp[(long)c * Nv] = (lo + hi) * inv;
    }
}

// ---------------- feat_sum + BN2 partial stats ----------------
__global__ void fsum_kernel(const float* __restrict__ sa, const float* __restrict__ sc,
                            const float* __restrict__ f1, const float* __restrict__ gamma1,
                            const float* __restrict__ gamma2, float* __restrict__ out,
                            float* __restrict__ ps, float* __restrict__ pss) {
    __shared__ float r1[256], r2[256];
    int bz = blockIdx.x;
    int b = bz >> 6, c = bz & 63;
    float g1 = gamma1[0], g2 = gamma2[0];
    long base = (long)bz * Nv;
    const float4* sa4 = (const float4*)(sa + base);
    const float4* sc4 = (const float4*)(sc + base);
    const float4* f4 = (const float4*)(f1 + base);
    float4* o4 = (float4*)(out + base);
    float s = 0.f, ss = 0.f;
    for (int i = threadIdx.x; i < 1600; i += 256) {
        float4 a = sa4[i], bb = sc4[i], f = f4[i];
        float4 v;
        v.x = g1 * a.x + g2 * bb.x + f.x;
        v.y = g1 * a.y + g2 * bb.y + f.y;
        v.z = g1 * a.z + g2 * bb.z + f.z;
        v.w = g1 * a.w + g2 * bb.w + f.w;
        o4[i] = v;
        s += v.x + v.y + v.z + v.w;
        ss += v.x * v.x + v.y * v.y + v.z * v.z + v.w * v.w;
    }
    int t = threadIdx.x;
    r1[t] = s; r2[t] = ss;
    __syncthreads();
    for (int st = 128; st > 0; st >>= 1) {
        if (t < st) { r1[t] += r1[t + st]; r2[t] += r2[t + st]; }
        __syncthreads();
    }
    if (t == 0) { ps[c * 64 + b] = r1[0]; pss[c * 64 + b] = r2[0]; }
}

// ---------------- host launch ----------------
extern "C" void kernel_launch(void* const* d_in, const int* in_sizes, int n_in,
                              void* d_out, int out_size) {
    const float* x     = (const float*)d_in[0];
    const float* Wc    = (const float*)d_in[1];
    const float* bn1g  = (const float*)d_in[2];
    const float* bn1b  = (const float*)d_in[3];
    const float* cqw   = (const float*)d_in[4];
    const float* cqb   = (const float*)d_in[5];
    const float* ckw   = (const float*)d_in[6];
    const float* ckb   = (const float*)d_in[7];
    const float* cvw   = (const float*)d_in[8];
    const float* cvb   = (const float*)d_in[9];
    const float* pqw   = (const float*)d_in[10];
    const float* pqb   = (const float*)d_in[11];
    const float* pkw   = (const float*)d_in[12];
    const float* pkb   = (const float*)d_in[13];
    const float* pvw   = (const float*)d_in[14];
    const float* pvb   = (const float*)d_in[15];
    const float* gamma1= (const float*)d_in[16];
    const float* gamma2= (const float*)d_in[17];
    const float* bn2g  = (const float*)d_in[18];
    const float* bn2b  = (const float*)d_in[19];
    const float* Wd    = (const float*)d_in[20];
    const float* bn3g  = (const float*)d_in[21];
    const float* bn3b  = (const float*)d_in[22];

    float* base = nullptr;
    cudaGetSymbolAddress((void**)&base, g_buf);
    float* t0    = base + OFF_T0;
    float* feat1 = base + OFF_FEAT1;
    float* vb    = base + OFF_VB;
    float* pvd   = base + OFF_PVD;
    float* sab   = base + OFF_SAB;
    float* scb   = base + OFF_SCB;
    float* qb    = base + OFF_QB;
    float* kb    = base + OFF_KB;
    float* pqd   = base + OFF_PQD;
    float* pkd   = base + OFF_PKD;
    float* attn  = base + OFF_ATTN;
    float* ps    = base + OFF_PS;
    float* pss   = base + OFF_PSS;
    float* scale = base + OFF_SCALE;
    float* shift = base + OFF_SHIFT;

    const int C3SMEM = 32 * 324 * 4 + 64 * 9 * 8 * 8;  // 78336
    cudaFuncSetAttribute(conv3x3_kernel<0>, cudaFuncAttributeMaxDynamicSharedMemorySize, C3SMEM);
    cudaFuncSetAttribute(conv3x3_kernel<1>, cudaFuncAttributeMaxDynamicSharedMemorySize, C3SMEM);

    dim3 cgrid(5, 5, Bv * 4), cblk(16, 16);

    // stage 1: conv_c -> BN1 -> ReLU
    conv3x3_kernel<0><<<cgrid, cblk, C3SMEM>>>(x, Wc, nullptr, nullptr, t0);
    stats_kernel<<<Bv * Cv, 256>>>(t0, ps, pss);
    bn_finalize<<<1, 64>>>(ps, pss, bn1g, bn1b, scale, shift, 2);
    bn_apply_kernel<<<800, 256>>>((const float4*)t0, (float4*)feat1, scale, shift, 1);

    // projections
    convqk_kernel<<<dim3(13, 8, Bv), 128>>>(feat1, cqw, cqb, ckw, ckb, qb, kb);
    conv1x1_kernel<64><<<dim3(Bv, 50), 128>>>(feat1, cvw, 0, cvb, vb);
    conv1x1_kernel<8><<<dim3(Bv, 50), 128>>>(feat1, pqw, 0, pqb, pqd);
    conv1x1_kernel<8><<<dim3(Bv, 50), 128>>>(feat1, pkw, 0, pkb, pkd);
    conv1x1_kernel<64><<<dim3(Bv, 50), 128>>>(feat1, pvw, 0, pvb, pvd);

    // CAM
    cam_kernel<<<Bv * Cv, 64>>>(qb, kb, attn);
    conv1x1_kernel<64><<<dim3(Bv, 50), 128>>>(vb, attn, 4096, nullptr, sab);

    // PAM (flash attention, f32x2, 128 thr)
    pam_kernel<<<dim3(50, 2, Bv), 128>>>(pqd, pkd, pvd, scb);

    // combine + BN2 (folded into conv_d input) -> conv_d -> BN3 -> ReLU
    fsum_kernel<<<Bv * Cv, 256>>>(sab, scb, feat1, gamma1, gamma2, t0, ps, pss);
    bn_finalize<<<1, 64>>>(ps, pss, bn2g, bn2b, scale, shift, 2);
    conv3x3_kernel<1><<<cgrid, cblk, C3SMEM>>>(t0, Wd, scale, shift, feat1);
    stats_kernel<<<Bv * Cv, 256>>>(feat1, ps, pss);
    bn_finalize<<<1, 64>>>(ps, pss, bn3g, bn3b, scale, shift, 2);
    bn_apply_kernel<<<800, 256>>>((const float4*)feat1, (float4*)d_out, scale, shift, 1);
}

// round 6
// speedup vs baseline: 3.8982x; 2.6110x over previous
#include <cuda_runtime.h>
#include <cuda_bf16.h>
#include <math.h>

#define Bv 2
#define Cv 64
#define Hv 80
#define Wv 80
#define Nv 6400
#define NQ 1600
#define NHWf 12800.0f
#define EPSV 1e-5f
#define L2E 1.44269504088896f

typedef unsigned long long ull;

// ---------------- f32x2 packed helpers ----------------
__device__ __forceinline__ ull pk2(float lo, float hi) {
    ull r; asm("mov.b64 %0,{%1,%2};" : "=l"(r) : "f"(lo), "f"(hi)); return r;
}
__device__ __forceinline__ void upk2(ull v, float& lo, float& hi) {
    asm("mov.b64 {%0,%1},%2;" : "=f"(lo), "=f"(hi) : "l"(v));
}
__device__ __forceinline__ ull fma2_(ull a, ull b, ull c) {
    ull d; asm("fma.rn.f32x2 %0,%1,%2,%3;" : "=l"(d) : "l"(a), "l"(b), "l"(c)); return d;
}
__device__ __forceinline__ float ex2_(float x) {
    float y; asm("ex2.approx.ftz.f32 %0,%1;" : "=f"(y) : "f"(x)); return y;
}
// pack two floats to bf16x2 word: lo = first (lower k index)
__device__ __forceinline__ unsigned pkbf(float lo, float hi) {
    unsigned d; asm("cvt.rn.bf16x2.f32 %0,%1,%2;" : "=r"(d) : "f"(hi), "f"(lo)); return d;
}
// mma m16n8k16 row.col f32.bf16.bf16.f32, accumulate in place
__device__ __forceinline__ void mma16816(float* c, unsigned a0, unsigned a1, unsigned a2,
                                         unsigned a3, unsigned b0, unsigned b1) {
    asm("mma.sync.aligned.m16n8k16.row.col.f32.bf16.bf16.f32 "
        "{%0,%1,%2,%3},{%4,%5,%6,%7},{%8,%9},{%0,%1,%2,%3};"
        : "+f"(c[0]), "+f"(c[1]), "+f"(c[2]), "+f"(c[3])
        : "r"(a0), "r"(a1), "r"(a2), "r"(a3), "r"(b0), "r"(b1));
}

// ---------------- scratch ----------------
#define OFF_T0     0
#define OFF_FEAT1  (OFF_T0   + Bv*Cv*Nv)
#define OFF_VB     (OFF_FEAT1+ Bv*Cv*Nv)
#define OFF_PVD    (OFF_VB   + Bv*Cv*Nv)
#define OFF_SAB    (OFF_PVD  + Bv*Cv*Nv)
#define OFF_SCB    (OFF_SAB  + Bv*Cv*Nv)
#define OFF_QB     (OFF_SCB  + Bv*Cv*Nv)
#define OFF_KB     (OFF_QB   + Bv*Cv*NQ)
#define OFF_PQD    (OFF_KB   + Bv*Cv*NQ)
#define OFF_PKD    (OFF_PQD  + Bv*8*Nv)
#define OFF_ATTN   (OFF_PKD  + Bv*8*Nv)
#define OFF_PS     (OFF_ATTN + Bv*Cv*Cv)
#define OFF_PSS    (OFF_PS   + 64*64)
#define OFF_SCALE  (OFF_PSS  + 64*64)
#define OFF_SHIFT  (OFF_SCALE+ 64)
#define OFF_QG     (OFF_SHIFT+ 64)          /* bf16 [B][N][16] = 102400 floats */
#define OFF_KG     (OFF_QG   + Bv*Nv*8)
#define OFF_VG     (OFF_KG   + Bv*Nv*8)     /* bf16 [B][C][N] = 409600 floats */
#define BUF_TOTAL  (OFF_VG   + Bv*Cv*Nv/2)

__device__ __align__(16) float g_buf[BUF_TOTAL];

// ---------------- conv3x3 (pad=1, no bias), 16 co per block, 2x32-channel smem chunks --
template <int AFFINE>
__global__ void conv3x3_kernel(const float* __restrict__ in, const float* __restrict__ w,
                               const float* __restrict__ scale, const float* __restrict__ shift,
                               float* __restrict__ out) {
    extern __shared__ float sm[];
    float* tile = sm;                                   // 32*324
    ull* w2 = (ull*)(sm + 32 * 324);                    // [ci*9+tap][8] co-pairs (all 64 ci)
    __shared__ float aff[128];
    int bz = blockIdx.z;
    int b = bz >> 2, co0 = (bz & 3) * 16;
    int t = threadIdx.y * 16 + threadIdx.x;

    float* wflat = (float*)w2;
    for (int i = t; i < 9216; i += 256) {
        int co = i & 15, r = i >> 4;
        wflat[r * 16 + co] = w[(co0 + co) * 576 + r];
    }
    if (AFFINE && t < 128) aff[t] = (t < 64) ? scale[t] : shift[t - 64];

    int oy0 = blockIdx.y * 16, ox0 = blockIdx.x * 16;
    const float* inb = in + (long)b * Cv * Nv;

    ull acc2[8];
#pragma unroll
    for (int c2 = 0; c2 < 8; c2++) acc2[c2] = pk2(0.f, 0.f);

    for (int chunk = 0; chunk < 2; chunk++) {
        int cbase = chunk * 32;
        __syncthreads();
        for (int i = t; i < 32 * 324; i += 256) {
            int ci = i / 324;
            int pos = i - ci * 324;
            int r = pos / 18, c2 = pos - r * 18;
            int gy = oy0 + r - 1, gx = ox0 + c2 - 1;
            float v = 0.f;
            if (gy >= 0 && gy < Hv && gx >= 0 && gx < Wv) {
                v = inb[(cbase + ci) * Nv + gy * Wv + gx];
                if (AFFINE) v = v * aff[cbase + ci] + aff[64 + cbase + ci];
            }
            tile[i] = v;
        }
        __syncthreads();

        for (int ci = 0; ci < 32; ci++) {
            const float* tp = tile + ci * 324 + threadIdx.y * 18 + threadIdx.x;
            float x[9];
#pragma unroll
            for (int ky = 0; ky < 3; ky++)
#pragma unroll
                for (int kx = 0; kx < 3; kx++) x[ky * 3 + kx] = tp[ky * 18 + kx];
            const ull* wr = w2 + (long)(cbase + ci) * 72;
#pragma unroll
            for (int tap = 0; tap < 9; tap++) {
                ull xd = pk2(x[tap], x[tap]);
#pragma unroll
                for (int c2 = 0; c2 < 8; c2++)
                    acc2[c2] = fma2_(xd, wr[tap * 8 + c2], acc2[c2]);
            }
        }
    }
    long obase = ((long)b * 64 + co0) * Nv + (oy0 + threadIdx.y) * Wv + ox0 + threadIdx.x;
#pragma unroll
    for (int c2 = 0; c2 < 8; c2++) {
        float lo, hi;
        upk2(acc2[c2], lo, hi);
        out[obase + (long)(2 * c2) * Nv] = lo;
        out[obase + (long)(2 * c2 + 1) * Nv] = hi;
    }
}

// ---------------- per-channel stats (sum, sumsq) ----------------
__global__ void stats_kernel(const float* __restrict__ in, float* __restrict__ ps,
                             float* __restrict__ pss) {
    __shared__ float r1[256], r2[256];
    int bz = blockIdx.x;
    int b = bz >> 6, c = bz & 63;
    const float4* p4 = (const float4*)(in + (long)bz * Nv);
    float s = 0.f, ss = 0.f;
    for (int i = threadIdx.x; i < 1600; i += 256) {
        float4 v = p4[i];
        s += v.x + v.y + v.z + v.w;
        ss += v.x * v.x + v.y * v.y + v.z * v.z + v.w * v.w;
    }
    int t = threadIdx.x;
    r1[t] = s; r2[t] = ss;
    __syncthreads();
    for (int st = 128; st > 0; st >>= 1) {
        if (t < st) { r1[t] += r1[t + st]; r2[t] += r2[t + st]; }
        __syncthreads();
    }
    if (t == 0) { ps[c * 64 + b] = r1[0]; pss[c * 64 + b] = r2[0]; }
}

// ---------------- BN finalize ----------------
__global__ void bn_finalize(const float* __restrict__ ps, const float* __restrict__ pss,
                            const float* __restrict__ g, const float* __restrict__ bb,
                            float* __restrict__ scale, float* __restrict__ shift, int nslots) {
    int c = threadIdx.x;
    float s = 0.f, ss = 0.f;
    for (int i = 0; i < nslots; i++) { s += ps[c * 64 + i]; ss += pss[c * 64 + i]; }
    float m = s / NHWf;
    float var = ss / NHWf - m * m;
    float rs = rsqrtf(var + EPSV);
    float sc = g[c] * rs;
    scale[c] = sc;
    shift[c] = bb[c] - m * sc;
}

// ---------------- BN apply (float4, +optional relu) ----------------
__global__ void bn_apply_kernel(const float4* __restrict__ in, float4* __restrict__ out,
                                const float* __restrict__ scale, const float* __restrict__ shift,
                                int relu) {
    int i = blockIdx.x * 256 + threadIdx.x;
    int c = (i / 1600) & 63;
    float sc = scale[c], sh = shift[c];
    float4 v = in[i];
    v.x = v.x * sc + sh; v.y = v.y * sc + sh; v.z = v.z * sc + sh; v.w = v.w * sc + sh;
    if (relu) {
        v.x = fmaxf(v.x, 0.f); v.y = fmaxf(v.y, 0.f);
        v.z = fmaxf(v.z, 0.f); v.w = fmaxf(v.w, 0.f);
    }
    out[i] = v;
}

// ---------------- fused conv2x2 stride2 (q and k) ----------------
__global__ void convqk_kernel(const float* __restrict__ in,
                              const float* __restrict__ wq, const float* __restrict__ bq,
                              const float* __restrict__ wk, const float* __restrict__ bk,
                              float* __restrict__ outq, float* __restrict__ outk) {
    __shared__ __align__(16) float wsm[4096];  // [ci*4+tap][16co]
    int conv = blockIdx.y >> 2;
    int co0 = (blockIdx.y & 3) * 16;
    int b = blockIdx.z;
    const float* w = conv ? wk : wq;
    const float* bias = conv ? bk : bq;
    float* out = conv ? outk : outq;

    for (int i = threadIdx.x; i < 4096; i += 128) {
        int co = i & 15, r = i >> 4;
        wsm[r * 16 + co] = w[(co0 + co) * 256 + r];
    }
    __syncthreads();

    int p = blockIdx.x * 128 + threadIdx.x;
    if (p >= NQ) return;
    int oy = p / 40, ox = p % 40;
    const float* inb = in + (long)b * Cv * Nv + (2 * oy) * Wv + 2 * ox;

    ull acc2[8];
    const ull* w2 = (const ull*)wsm;
#pragma unroll
    for (int c2 = 0; c2 < 8; c2++) acc2[c2] = pk2(bias[co0 + 2 * c2], bias[co0 + 2 * c2 + 1]);

#pragma unroll 4
    for (int ci = 0; ci < 64; ci++) {
        float2 a = *(const float2*)(inb + ci * Nv);
        float2 bb2 = *(const float2*)(inb + ci * Nv + Wv);
        ull x0 = pk2(a.x, a.x), x1 = pk2(a.y, a.y);
        ull x2 = pk2(bb2.x, bb2.x), x3 = pk2(bb2.y, bb2.y);
        const ull* wr = w2 + ci * 32;
#pragma unroll
        for (int c2 = 0; c2 < 8; c2++) {
            ull a2 = fma2_(x0, wr[c2], acc2[c2]);
            a2 = fma2_(x1, wr[8 + c2], a2);
            a2 = fma2_(x2, wr[16 + c2], a2);
            acc2[c2] = fma2_(x3, wr[24 + c2], a2);
        }
    }
    long obase = ((long)b * 64 + co0) * NQ + p;
#pragma unroll
    for (int c2 = 0; c2 < 8; c2++) {
        float lo, hi;
        upk2(acc2[c2], lo, hi);
        out[obase + (long)(2 * c2) * NQ] = lo;
        out[obase + (long)(2 * c2 + 1) * NQ] = hi;
    }
}

// ---------------- conv1x1 (CO outputs, 64 inputs); weights optionally per-batch -------
template <int CO>
__global__ void conv1x1_kernel(const float* __restrict__ in, const float* __restrict__ w,
                               int wstride, const float* __restrict__ bias,
                               float* __restrict__ out) {
    __shared__ __align__(16) float wsm[CO * 64];
    int b = blockIdx.x;
    int n = blockIdx.y * 128 + threadIdx.x;
    const float* wb = w + (long)b * wstride;
    for (int i = threadIdx.x; i < CO * 64; i += 128) {
        int co = i >> 6, ci = i & 63;
        wsm[ci * CO + co] = wb[i];
    }
    __syncthreads();
    float acc[CO];
#pragma unroll
    for (int co = 0; co < CO; co++) acc[co] = bias ? bias[co] : 0.f;
    const float* inb = in + (long)b * 64 * Nv + n;
    const float4* wsm4 = (const float4*)wsm;
#pragma unroll 4
    for (int ci = 0; ci < 64; ci++) {
        float xv = inb[ci * Nv];
#pragma unroll
        for (int c4 = 0; c4 < CO / 4; c4++) {
            float4 w4 = wsm4[ci * (CO / 4) + c4];
            acc[c4 * 4 + 0] += w4.x * xv;
            acc[c4 * 4 + 1] += w4.y * xv;
            acc[c4 * 4 + 2] += w4.z * xv;
            acc[c4 * 4 + 3] += w4.w * xv;
        }
    }
    float* ob = out + (long)b * CO * Nv + n;
#pragma unroll
    for (int co = 0; co < CO; co++) ob[co * Nv] = acc[co];
}

// ---------------- CAM energy + softmax ----------------
__global__ void cam_kernel(const float* __restrict__ q, const float* __restrict__ k,
                           float* __restrict__ attn) {
    __shared__ __align__(16) float qsm[NQ];
    __shared__ float er[64];
    __shared__ float pe[64];
    int b = blockIdx.x >> 6, c = blockIdx.x & 63;
    const float* qr = q + (long)(b * 64 + c) * NQ;
    for (int i = threadIdx.x; i < NQ; i += 64) qsm[i] = qr[i];
    __syncthreads();
    int d = threadIdx.x;
    const float4* kr = (const float4*)(k + (long)(b * 64 + d) * NQ);
    const float4* q4 = (const float4*)qsm;
    float s = 0.f;
#pragma unroll 4
    for (int i = 0; i < NQ / 4; i++) {
        float4 kv = kr[i];
        float4 qv = q4[i];
        s += qv.x * kv.x + qv.y * kv.y + qv.z * kv.z + qv.w * kv.w;
    }
    er[d] = s;
    __syncthreads();
    float mn = er[0];
    for (int i = 1; i < 64; i++) mn = fminf(mn, er[i]);
    float p = __expf(mn - s);
    pe[d] = p;
    __syncthreads();
    float sum = 0.f;
    for (int i = 0; i < 64; i++) sum += pe[i];
    attn[(long)(b * 64 + c) * 64 + d] = p / sum;
}

// ---------------- PAM prep: Q/K -> bf16 [b][n][16] (e padded to 16), Q scaled by L2E --
__global__ void qk_prep(const float* __restrict__ pqd, const float* __restrict__ pkd,
                        __nv_bfloat16* __restrict__ qg, __nv_bfloat16* __restrict__ kg) {
    int b = blockIdx.y, which = blockIdx.z;
    int n = blockIdx.x * 128 + threadIdx.x;
    const float* src = (which ? pkd : pqd) + (long)b * 8 * Nv + n;
    __nv_bfloat16* dst = (which ? kg : qg) + ((long)b * Nv + n) * 16;
    float sc = which ? 1.f : L2E;
    unsigned o[8];
#pragma unroll
    for (int e = 0; e < 4; e++) {
        float v0 = src[(2 * e) * Nv] * sc;
        float v1 = src[(2 * e + 1) * Nv] * sc;
        o[e] = pkbf(v0, v1);
    }
    o[4] = o[5] = o[6] = o[7] = 0u;
    uint4* d4 = (uint4*)dst;
    d4[0] = make_uint4(o[0], o[1], o[2], o[3]);
    d4[1] = make_uint4(o[4], o[5], o[6], o[7]);
}

// ---------------- PAM prep: V -> bf16 [b][c][n] ----------------
__global__ void v_prep(const float4* __restrict__ pvd, uint2* __restrict__ vg) {
    int i = blockIdx.x * 256 + threadIdx.x;   // grid 800 -> 204800 float4
    float4 v = pvd[i];
    vg[i] = make_uint2(pkbf(v.x, v.y), pkbf(v.z, v.w));
}

// ---------------- PAM: flash attention via mma.sync bf16 ----------------
// block 128 thr (4 warps x 16q = 64 q), grid (100, B). All 64 channels per warp.
__global__ void __launch_bounds__(128) pam_mma_kernel(
    const __nv_bfloat16* __restrict__ qg, const __nv_bfloat16* __restrict__ kg,
    const __nv_bfloat16* __restrict__ vg, float* __restrict__ sc) {
    __shared__ __align__(16) __nv_bfloat16 Qs[64 * 16];   // [q][e]
    __shared__ __align__(16) __nv_bfloat16 Ks[64 * 16];   // [j][e]
    __shared__ __align__(16) __nv_bfloat16 Vs[64 * 72];   // [c][j], stride 72 (conflict-free)
    int b = blockIdx.y;
    int q0 = blockIdx.x * 64;
    int t = threadIdx.x, w = t >> 5, lane = t & 31;
    int g = lane >> 2, ti = lane & 3;

    // load Q tile once: 64 rows x 32B = 128 x 16B chunks
    ((uint4*)Qs)[t] = ((const uint4*)(qg + ((long)b * Nv + q0) * 16))[t];
    __syncthreads();

    // A-fragments of Q for this warp (rows w*16 .. w*16+15)
    unsigned qa0, qa1, qa2, qa3;
    {
        const unsigned* qw = (const unsigned*)Qs;
        int r = w * 16 + g;
        qa0 = qw[r * 8 + ti];
        qa1 = qw[(r + 8) * 8 + ti];
        qa2 = qw[r * 8 + ti + 4];
        qa3 = qw[(r + 8) * 8 + ti + 4];
    }

    float o[8][4];
#pragma unroll
    for (int nc = 0; nc < 8; nc++) { o[nc][0] = o[nc][1] = o[nc][2] = o[nc][3] = 0.f; }
    float li_lo = 0.f, li_hi = 0.f, mi_lo = -1e30f, mi_hi = -1e30f;

    for (int j0 = 0; j0 < Nv; j0 += 64) {
        __syncthreads();
        // fill K tile: 128 x 16B
        ((uint4*)Ks)[t] = ((const uint4*)(kg + ((long)b * Nv + j0) * 16))[t];
        // fill V tile: 64 c rows x 8 x 16B chunks
#pragma unroll
        for (int i = t; i < 512; i += 128) {
            int c = i >> 3, h = i & 7;
            uint4 v = *(const uint4*)(vg + ((long)(b * 64 + c)) * Nv + j0 + h * 8);
            *(uint4*)(Vs + c * 72 + h * 8) = v;
        }
        __syncthreads();

        // QK: S[16q][64j] fragments
        float s[8][4];
        const unsigned* kw = (const unsigned*)Ks;
#pragma unroll
        for (int nt = 0; nt < 8; nt++) {
            int j = nt * 8 + g;
            unsigned b0 = kw[j * 8 + ti];
            unsigned b1 = kw[j * 8 + ti + 4];
            s[nt][0] = s[nt][1] = s[nt][2] = s[nt][3] = 0.f;
            mma16816(s[nt], qa0, qa1, qa2, qa3, b0, b1);
        }
        // row max (thread-local then quad shfl)
        float mlo = s[0][0], mhi = s[0][2];
#pragma unroll
        for (int nt = 0; nt < 8; nt++) {
            mlo = fmaxf(mlo, fmaxf(s[nt][0], s[nt][1]));
            mhi = fmaxf(mhi, fmaxf(s[nt][2], s[nt][3]));
        }
        mlo = fmaxf(mlo, __shfl_xor_sync(0xffffffffu, mlo, 1));
        mlo = fmaxf(mlo, __shfl_xor_sync(0xffffffffu, mlo, 2));
        mhi = fmaxf(mhi, __shfl_xor_sync(0xffffffffu, mhi, 1));
        mhi = fmaxf(mhi, __shfl_xor_sync(0xffffffffu, mhi, 2));
        float nmlo = fmaxf(mi_lo, mlo), nmhi = fmaxf(mi_hi, mhi);
        float clo = ex2_(mi_lo - nmlo), chi = ex2_(mi_hi - nmhi);
        li_lo *= clo; li_hi *= chi;
#pragma unroll
        for (int nc = 0; nc < 8; nc++) {
            o[nc][0] *= clo; o[nc][1] *= clo; o[nc][2] *= chi; o[nc][3] *= chi;
        }
        // exp + pack P fragments
        unsigned pa[8][2];
#pragma unroll
        for (int nt = 0; nt < 8; nt++) {
            float p0 = ex2_(s[nt][0] - nmlo);
            float p1 = ex2_(s[nt][1] - nmlo);
            float p2 = ex2_(s[nt][2] - nmhi);
            float p3 = ex2_(s[nt][3] - nmhi);
            li_lo += p0 + p1;
            li_hi += p2 + p3;
            pa[nt][0] = pkbf(p0, p1);
            pa[nt][1] = pkbf(p2, p3);
        }
        mi_lo = nmlo; mi_hi = nmhi;

        // PV: O[16q][64c] += P[16q][64j] * V[64c][64j]^T
        const unsigned* vw = (const unsigned*)Vs;
#pragma unroll
        for (int nc = 0; nc < 8; nc++) {
            int c = nc * 8 + g;
            const unsigned* vr = vw + c * 36 + ti;
#pragma unroll
            for (int i = 0; i < 4; i++) {
                unsigned b0 = vr[8 * i];
                unsigned b1 = vr[8 * i + 4];
                mma16816(o[nc], pa[2 * i][0], pa[2 * i][1], pa[2 * i + 1][0], pa[2 * i + 1][1],
                         b0, b1);
            }
        }
    }
    // finalize: quad-reduce li, normalize, write
    li_lo += __shfl_xor_sync(0xffffffffu, li_lo, 1);
    li_lo += __shfl_xor_sync(0xffffffffu, li_lo, 2);
    li_hi += __shfl_xor_sync(0xffffffffu, li_hi, 1);
    li_hi += __shfl_xor_sync(0xffffffffu, li_hi, 2);
    float inv_lo = 1.f / li_lo, inv_hi = 1.f / li_hi;
    int q = q0 + w * 16 + g;
#pragma unroll
    for (int nc = 0; nc < 8; nc++) {
        int c = nc * 8 + ti * 2;
        sc[((long)(b * 64 + c)) * Nv + q] = o[nc][0] * inv_lo;
        sc[((long)(b * 64 + c + 1)) * Nv + q] = o[nc][1] * inv_lo;
        sc[((long)(b * 64 + c)) * Nv + q + 8] = o[nc][2] * inv_hi;
        sc[((long)(b * 64 + c + 1)) * Nv + q + 8] = o[nc][3] * inv_hi;
    }
}

// ---------------- feat_sum + BN2 partial stats ----------------
__global__ void fsum_kernel(const float* __restrict__ sa, const float* __restrict__ sc,
                            const float* __restrict__ f1, const float* __restrict__ gamma1,
                            const float* __restrict__ gamma2, float* __restrict__ out,
                            float* __restrict__ ps, float* __restrict__ pss) {
    __shared__ float r1[256], r2[256];
    int bz = blockIdx.x;
    int b = bz >> 6, c = bz & 63;
    float g1 = gamma1[0], g2 = gamma2[0];
    long base = (long)bz * Nv;
    const float4* sa4 = (const float4*)(sa + base);
    const float4* sc4 = (const float4*)(sc + base);
    const float4* f4 = (const float4*)(f1 + base);
    float4* o4 = (float4*)(out + base);
    float s = 0.f, ss = 0.f;
    for (int i = threadIdx.x; i < 1600; i += 256) {
        float4 a = sa4[i], bb = sc4[i], f = f4[i];
        float4 v;
        v.x = g1 * a.x + g2 * bb.x + f.x;
        v.y = g1 * a.y + g2 * bb.y + f.y;
        v.z = g1 * a.z + g2 * bb.z + f.z;
        v.w = g1 * a.w + g2 * bb.w + f.w;
        o4[i] = v;
        s += v.x + v.y + v.z + v.w;
        ss += v.x * v.x + v.y * v.y + v.z * v.z + v.w * v.w;
    }
    int t = threadIdx.x;
    r1[t] = s; r2[t] = ss;
    __syncthreads();
    for (int st = 128; st > 0; st >>= 1) {
        if (t < st) { r1[t] += r1[t + st]; r2[t] += r2[t + st]; }
        __syncthreads();
    }
    if (t == 0) { ps[c * 64 + b] = r1[0]; pss[c * 64 + b] = r2[0]; }
}

// ---------------- host launch ----------------
extern "C" void kernel_launch(void* const* d_in, const int* in_sizes, int n_in,
                              void* d_out, int out_size) {
    const float* x     = (const float*)d_in[0];
    const float* Wc    = (const float*)d_in[1];
    const float* bn1g  = (const float*)d_in[2];
    const float* bn1b  = (const float*)d_in[3];
    const float* cqw   = (const float*)d_in[4];
    const float* cqb   = (const float*)d_in[5];
    const float* ckw   = (const float*)d_in[6];
    const float* ckb   = (const float*)d_in[7];
    const float* cvw   = (const float*)d_in[8];
    const float* cvb   = (const float*)d_in[9];
    const float* pqw   = (const float*)d_in[10];
    const float* pqb   = (const float*)d_in[11];
    const float* pkw   = (const float*)d_in[12];
    const float* pkb   = (const float*)d_in[13];
    const float* pvw   = (const float*)d_in[14];
    const float* pvb   = (const float*)d_in[15];
    const float* gamma1= (const float*)d_in[16];
    const float* gamma2= (const float*)d_in[17];
    const float* bn2g  = (const float*)d_in[18];
    const float* bn2b  = (const float*)d_in[19];
    const float* Wd    = (const float*)d_in[20];
    const float* bn3g  = (const float*)d_in[21];
    const float* bn3b  = (const float*)d_in[22];

    float* base = nullptr;
    cudaGetSymbolAddress((void**)&base, g_buf);
    float* t0    = base + OFF_T0;
    float* feat1 = base + OFF_FEAT1;
    float* vb    = base + OFF_VB;
    float* pvd   = base + OFF_PVD;
    float* sab   = base + OFF_SAB;
    float* scb   = base + OFF_SCB;
    float* qb    = base + OFF_QB;
    float* kb    = base + OFF_KB;
    float* pqd   = base + OFF_PQD;
    float* pkd   = base + OFF_PKD;
    float* attn  = base + OFF_ATTN;
    float* ps    = base + OFF_PS;
    float* pss   = base + OFF_PSS;
    float* scale = base + OFF_SCALE;
    float* shift = base + OFF_SHIFT;
    __nv_bfloat16* qg = (__nv_bfloat16*)(base + OFF_QG);
    __nv_bfloat16* kg = (__nv_bfloat16*)(base + OFF_KG);
    __nv_bfloat16* vg = (__nv_bfloat16*)(base + OFF_VG);

    const int C3SMEM = 32 * 324 * 4 + 64 * 9 * 8 * 8;  // 78336
    cudaFuncSetAttribute(conv3x3_kernel<0>, cudaFuncAttributeMaxDynamicSharedMemorySize, C3SMEM);
    cudaFuncSetAttribute(conv3x3_kernel<1>, cudaFuncAttributeMaxDynamicSharedMemorySize, C3SMEM);

    dim3 cgrid(5, 5, Bv * 4), cblk(16, 16);

    // stage 1: conv_c -> BN1 -> ReLU
    conv3x3_kernel<0><<<cgrid, cblk, C3SMEM>>>(x, Wc, nullptr, nullptr, t0);
    stats_kernel<<<Bv * Cv, 256>>>(t0, ps, pss);
    bn_finalize<<<1, 64>>>(ps, pss, bn1g, bn1b, scale, shift, 2);
    bn_apply_kernel<<<800, 256>>>((const float4*)t0, (float4*)feat1, scale, shift, 1);

    // projections
    convqk_kernel<<<dim3(13, 8, Bv), 128>>>(feat1, cqw, cqb, ckw, ckb, qb, kb);
    conv1x1_kernel<64><<<dim3(Bv, 50), 128>>>(feat1, cvw, 0, cvb, vb);
    conv1x1_kernel<8><<<dim3(Bv, 50), 128>>>(feat1, pqw, 0, pqb, pqd);
    conv1x1_kernel<8><<<dim3(Bv, 50), 128>>>(feat1, pkw, 0, pkb, pkd);
    conv1x1_kernel<64><<<dim3(Bv, 50), 128>>>(feat1, pvw, 0, pvb, pvd);

    // CAM
    cam_kernel<<<Bv * Cv, 64>>>(qb, kb, attn);
    conv1x1_kernel<64><<<dim3(Bv, 50), 128>>>(vb, attn, 4096, nullptr, sab);

    // PAM (flash attention via tensor cores)
    qk_prep<<<dim3(50, Bv, 2), 128>>>(pqd, pkd, qg, kg);
    v_prep<<<800, 256>>>((const float4*)pvd, (uint2*)vg);
    pam_mma_kernel<<<dim3(100, Bv), 128>>>(qg, kg, vg, scb);

    // combine + BN2 (folded into conv_d input) -> conv_d -> BN3 -> ReLU
    fsum_kernel<<<Bv * Cv, 256>>>(sab, scb, feat1, gamma1, gamma2, t0, ps, pss);
    bn_finalize<<<1, 64>>>(ps, pss, bn2g, bn2b, scale, shift, 2);
    conv3x3_kernel<1><<<cgrid, cblk, C3SMEM>>>(t0, Wd, scale, shift, feat1);
    stats_kernel<<<Bv * Cv, 256>>>(feat1, ps, pss);
    bn_finalize<<<1, 64>>>(ps, pss, bn3g, bn3b, scale, shift, 2);
    bn_apply_kernel<<<800, 256>>>((const float4*)feat1, (float4*)d_out, scale, shift, 1);
}

// round 7
// speedup vs baseline: 4.1778x; 1.0717x over previous
#include <cuda_runtime.h>
#include <cuda_bf16.h>
#include <math.h>

#define Bv 2
#define Cv 64
#define Hv 80
#define Wv 80
#define Nv 6400
#define NQ 1600
#define NHWf 12800.0f
#define EPSV 1e-5f
#define L2E 1.44269504088896f

typedef unsigned long long ull;

// ---------------- packed helpers ----------------
__device__ __forceinline__ ull pk2(float lo, float hi) {
    ull r; asm("mov.b64 %0,{%1,%2};" : "=l"(r) : "f"(lo), "f"(hi)); return r;
}
__device__ __forceinline__ void upk2(ull v, float& lo, float& hi) {
    asm("mov.b64 {%0,%1},%2;" : "=f"(lo), "=f"(hi) : "l"(v));
}
__device__ __forceinline__ ull fma2_(ull a, ull b, ull c) {
    ull d; asm("fma.rn.f32x2 %0,%1,%2,%3;" : "=l"(d) : "l"(a), "l"(b), "l"(c)); return d;
}
__device__ __forceinline__ float ex2_(float x) {
    float y; asm("ex2.approx.ftz.f32 %0,%1;" : "=f"(y) : "f"(x)); return y;
}
// pack two floats to bf16x2 word: lo = first (lower k index)
__device__ __forceinline__ unsigned pkbf(float lo, float hi) {
    unsigned d; asm("cvt.rn.bf16x2.f32 %0,%1,%2;" : "=r"(d) : "f"(hi), "f"(lo)); return d;
}
__device__ __forceinline__ void mma16816(float* c, unsigned a0, unsigned a1, unsigned a2,
                                         unsigned a3, unsigned b0, unsigned b1) {
    asm("mma.sync.aligned.m16n8k16.row.col.f32.bf16.bf16.f32 "
        "{%0,%1,%2,%3},{%4,%5,%6,%7},{%8,%9},{%0,%1,%2,%3};"
        : "+f"(c[0]), "+f"(c[1]), "+f"(c[2]), "+f"(c[3])
        : "r"(a0), "r"(a1), "r"(a2), "r"(a3), "r"(b0), "r"(b1));
}

// ---------------- scratch ----------------
#define OFF_T0     0
#define OFF_T1     (OFF_T0   + Bv*Cv*Nv)
#define OFF_VB     (OFF_T1   + Bv*Cv*Nv)
#define OFF_SAB    (OFF_VB   + Bv*Cv*Nv)
#define OFF_SCB    (OFF_SAB  + Bv*Cv*Nv)
#define OFF_QB     (OFF_SCB  + Bv*Cv*Nv)
#define OFF_KB     (OFF_QB   + Bv*Cv*NQ)
#define OFF_ATTN   (OFF_KB   + Bv*Cv*NQ)
#define OFF_PS     (OFF_ATTN + Bv*Cv*Cv)
#define OFF_PSS    (OFF_PS   + 64*64)
#define OFF_SC1    (OFF_PSS  + 64*64)
#define OFF_SH1    (OFF_SC1  + 64)
#define OFF_SC2    (OFF_SH1  + 64)
#define OFF_SH2    (OFF_SC2  + 64)
#define OFF_SC3    (OFF_SH2  + 64)
#define OFF_SH3    (OFF_SC3  + 64)
#define OFF_QG     (OFF_SH3  + 64)          /* bf16 [B][N][16] */
#define OFF_KG     (OFF_QG   + Bv*Nv*8)
#define OFF_VG     (OFF_KG   + Bv*Nv*8)     /* bf16 [B][C][N] */
#define BUF_TOTAL  (OFF_VG   + Bv*Cv*Nv/2)

__device__ __align__(16) float g_buf[BUF_TOTAL];

// ---------------- conv3x3 (pad=1, no bias), 16 co per block, 2x32-channel smem chunks --
template <int AFFINE>
__global__ void conv3x3_kernel(const float* __restrict__ in, const float* __restrict__ w,
                               const float* __restrict__ scale, const float* __restrict__ shift,
                               float* __restrict__ out) {
    extern __shared__ float sm[];
    float* tile = sm;                                   // 32*324
    ull* w2 = (ull*)(sm + 32 * 324);                    // [ci*9+tap][8] co-pairs (all 64 ci)
    __shared__ float aff[128];
    int bz = blockIdx.z;
    int b = bz >> 2, co0 = (bz & 3) * 16;
    int t = threadIdx.y * 16 + threadIdx.x;

    float* wflat = (float*)w2;
    for (int i = t; i < 9216; i += 256) {
        int co = i & 15, r = i >> 4;
        wflat[r * 16 + co] = w[(co0 + co) * 576 + r];
    }
    if (AFFINE && t < 128) aff[t] = (t < 64) ? scale[t] : shift[t - 64];

    int oy0 = blockIdx.y * 16, ox0 = blockIdx.x * 16;
    const float* inb = in + (long)b * Cv * Nv;

    ull acc2[8];
#pragma unroll
    for (int c2 = 0; c2 < 8; c2++) acc2[c2] = pk2(0.f, 0.f);

    for (int chunk = 0; chunk < 2; chunk++) {
        int cbase = chunk * 32;
        __syncthreads();
        for (int i = t; i < 32 * 324; i += 256) {
            int ci = i / 324;
            int pos = i - ci * 324;
            int r = pos / 18, c2 = pos - r * 18;
            int gy = oy0 + r - 1, gx = ox0 + c2 - 1;
            float v = 0.f;
            if (gy >= 0 && gy < Hv && gx >= 0 && gx < Wv) {
                v = inb[(cbase + ci) * Nv + gy * Wv + gx];
                if (AFFINE) v = v * aff[cbase + ci] + aff[64 + cbase + ci];
            }
            tile[i] = v;
        }
        __syncthreads();

        for (int ci = 0; ci < 32; ci++) {
            const float* tp = tile + ci * 324 + threadIdx.y * 18 + threadIdx.x;
            float x[9];
#pragma unroll
            for (int ky = 0; ky < 3; ky++)
#pragma unroll
                for (int kx = 0; kx < 3; kx++) x[ky * 3 + kx] = tp[ky * 18 + kx];
            const ull* wr = w2 + (long)(cbase + ci) * 72;
#pragma unroll
            for (int tap = 0; tap < 9; tap++) {
                ull xd = pk2(x[tap], x[tap]);
#pragma unroll
                for (int c2 = 0; c2 < 8; c2++)
                    acc2[c2] = fma2_(xd, wr[tap * 8 + c2], acc2[c2]);
            }
        }
    }
    long obase = ((long)b * 64 + co0) * Nv + (oy0 + threadIdx.y) * Wv + ox0 + threadIdx.x;
#pragma unroll
    for (int c2 = 0; c2 < 8; c2++) {
        float lo, hi;
        upk2(acc2[c2], lo, hi);
        out[obase + (long)(2 * c2) * Nv] = lo;
        out[obase + (long)(2 * c2 + 1) * Nv] = hi;
    }
}

// ---------------- per-channel stats (sum, sumsq) ----------------
__global__ void stats_kernel(const float* __restrict__ in, float* __restrict__ ps,
                             float* __restrict__ pss) {
    __shared__ float r1[256], r2[256];
    int bz = blockIdx.x;
    int b = bz >> 6, c = bz & 63;
    const float4* p4 = (const float4*)(in + (long)bz * Nv);
    float s = 0.f, ss = 0.f;
    for (int i = threadIdx.x; i < 1600; i += 256) {
        float4 v = p4[i];
        s += v.x + v.y + v.z + v.w;
        ss += v.x * v.x + v.y * v.y + v.z * v.z + v.w * v.w;
    }
    int t = threadIdx.x;
    r1[t] = s; r2[t] = ss;
    __syncthreads();
    for (int st = 128; st > 0; st >>= 1) {
        if (t < st) { r1[t] += r1[t + st]; r2[t] += r2[t + st]; }
        __syncthreads();
    }
    if (t == 0) { ps[c * 64 + b] = r1[0]; pss[c * 64 + b] = r2[0]; }
}

// ---------------- BN finalize ----------------
__global__ void bn_finalize(const float* __restrict__ ps, const float* __restrict__ pss,
                            const float* __restrict__ g, const float* __restrict__ bb,
                            float* __restrict__ scale, float* __restrict__ shift, int nslots) {
    int c = threadIdx.x;
    float s = 0.f, ss = 0.f;
    for (int i = 0; i < nslots; i++) { s += ps[c * 64 + i]; ss += pss[c * 64 + i]; }
    float m = s / NHWf;
    float var = ss / NHWf - m * m;
    float rs = rsqrtf(var + EPSV);
    float sc = g[c] * rs;
    scale[c] = sc;
    shift[c] = bb[c] - m * sc;
}

// ---------------- BN apply (float4, +relu) — final output only ----------------
__global__ void bn_apply_kernel(const float4* __restrict__ in, float4* __restrict__ out,
                                const float* __restrict__ scale, const float* __restrict__ shift) {
    int i = blockIdx.x * 256 + threadIdx.x;
    int c = (i / 1600) & 63;
    float sc = scale[c], sh = shift[c];
    float4 v = in[i];
    v.x = fmaxf(v.x * sc + sh, 0.f);
    v.y = fmaxf(v.y * sc + sh, 0.f);
    v.z = fmaxf(v.z * sc + sh, 0.f);
    v.w = fmaxf(v.w * sc + sh, 0.f);
    out[i] = v;
}

// ---------------- fused conv2x2 stride2 (q and k), affine-relu input ----------------
// grid (13, 8, B): y = conv*4 + cogrp(16 co). block 128.
__global__ void convqk_kernel(const float* __restrict__ in,
                              const float* __restrict__ wq, const float* __restrict__ bq,
                              const float* __restrict__ wk, const float* __restrict__ bk,
                              const float* __restrict__ sc1, const float* __restrict__ sh1,
                              float* __restrict__ outq, float* __restrict__ outk) {
    __shared__ __align__(16) float wsm[4096];  // [ci*4+tap][16co]
    __shared__ float aff[128];
    int conv = blockIdx.y >> 2;
    int co0 = (blockIdx.y & 3) * 16;
    int b = blockIdx.z;
    const float* w = conv ? wk : wq;
    const float* bias = conv ? bk : bq;
    float* out = conv ? outk : outq;

    for (int i = threadIdx.x; i < 4096; i += 128) {
        int co = i & 15, r = i >> 4;
        wsm[r * 16 + co] = w[(co0 + co) * 256 + r];
    }
    aff[threadIdx.x] = (threadIdx.x < 64) ? sc1[threadIdx.x] : sh1[threadIdx.x - 64];
    __syncthreads();

    int p = blockIdx.x * 128 + threadIdx.x;
    if (p >= NQ) return;
    int oy = p / 40, ox = p % 40;
    const float* inb = in + (long)b * Cv * Nv + (2 * oy) * Wv + 2 * ox;

    ull acc2[8];
    const ull* w2 = (const ull*)wsm;
#pragma unroll
    for (int c2 = 0; c2 < 8; c2++) acc2[c2] = pk2(bias[co0 + 2 * c2], bias[co0 + 2 * c2 + 1]);

#pragma unroll 4
    for (int ci = 0; ci < 64; ci++) {
        float s = aff[ci], h = aff[64 + ci];
        float2 a = *(const float2*)(inb + ci * Nv);
        float2 bb2 = *(const float2*)(inb + ci * Nv + Wv);
        float v0 = fmaxf(a.x * s + h, 0.f), v1 = fmaxf(a.y * s + h, 0.f);
        float v2 = fmaxf(bb2.x * s + h, 0.f), v3 = fmaxf(bb2.y * s + h, 0.f);
        ull x0 = pk2(v0, v0), x1 = pk2(v1, v1);
        ull x2 = pk2(v2, v2), x3 = pk2(v3, v3);
        const ull* wr = w2 + ci * 32;
#pragma unroll
        for (int c2 = 0; c2 < 8; c2++) {
            ull a2 = fma2_(x0, wr[c2], acc2[c2]);
            a2 = fma2_(x1, wr[8 + c2], a2);
            a2 = fma2_(x2, wr[16 + c2], a2);
            acc2[c2] = fma2_(x3, wr[24 + c2], a2);
        }
    }
    long obase = ((long)b * 64 + co0) * NQ + p;
#pragma unroll
    for (int c2 = 0; c2 < 8; c2++) {
        float lo, hi;
        upk2(acc2[c2], lo, hi);
        out[obase + (long)(2 * c2) * NQ] = lo;
        out[obase + (long)(2 * c2 + 1) * NQ] = hi;
    }
}

// ---------------- fused pq+pk 1x1 conv (8 outs each), affine-relu input, bf16 out -----
// grid (B, 50), block 128. Writes qg (scaled by L2E) and kg in [n][16] bf16 layout.
__global__ void convqk1x1_kernel(const float* __restrict__ in,
                                 const float* __restrict__ wq, const float* __restrict__ bq,
                                 const float* __restrict__ wk, const float* __restrict__ bk,
                                 const float* __restrict__ sc1, const float* __restrict__ sh1,
                                 __nv_bfloat16* __restrict__ qg, __nv_bfloat16* __restrict__ kg) {
    __shared__ __align__(16) float wsmq[512];  // [ci*8+co]
    __shared__ __align__(16) float wsmk[512];
    __shared__ float aff[128];
    int b = blockIdx.x;
    int n = blockIdx.y * 128 + threadIdx.x;
    for (int i = threadIdx.x; i < 512; i += 128) {
        int co = i >> 6, ci = i & 63;
        wsmq[ci * 8 + co] = wq[i];
        wsmk[ci * 8 + co] = wk[i];
    }
    aff[threadIdx.x] = (threadIdx.x < 64) ? sc1[threadIdx.x] : sh1[threadIdx.x - 64];
    __syncthreads();
    float aq[8], ak[8];
#pragma unroll
    for (int j = 0; j < 8; j++) { aq[j] = bq[j]; ak[j] = bk[j]; }
    const float* inb = in + (long)b * 64 * Nv + n;
    const float4* wq4 = (const float4*)wsmq;
    const float4* wk4 = (const float4*)wsmk;
#pragma unroll 4
    for (int ci = 0; ci < 64; ci++) {
        float xv = fmaxf(inb[ci * Nv] * aff[ci] + aff[64 + ci], 0.f);
#pragma unroll
        for (int c4 = 0; c4 < 2; c4++) {
            float4 w4 = wq4[ci * 2 + c4];
            aq[c4 * 4 + 0] += w4.x * xv; aq[c4 * 4 + 1] += w4.y * xv;
            aq[c4 * 4 + 2] += w4.z * xv; aq[c4 * 4 + 3] += w4.w * xv;
            float4 k4 = wk4[ci * 2 + c4];
            ak[c4 * 4 + 0] += k4.x * xv; ak[c4 * 4 + 1] += k4.y * xv;
            ak[c4 * 4 + 2] += k4.z * xv; ak[c4 * 4 + 3] += k4.w * xv;
        }
    }
    uint4* qd = (uint4*)(qg + ((long)b * Nv + n) * 16);
    uint4* kd = (uint4*)(kg + ((long)b * Nv + n) * 16);
    qd[0] = make_uint4(pkbf(aq[0] * L2E, aq[1] * L2E), pkbf(aq[2] * L2E, aq[3] * L2E),
                       pkbf(aq[4] * L2E, aq[5] * L2E), pkbf(aq[6] * L2E, aq[7] * L2E));
    qd[1] = make_uint4(0u, 0u, 0u, 0u);
    kd[0] = make_uint4(pkbf(ak[0], ak[1]), pkbf(ak[2], ak[3]),
                       pkbf(ak[4], ak[5]), pkbf(ak[6], ak[7]));
    kd[1] = make_uint4(0u, 0u, 0u, 0u);
}

// ---------------- conv1x1 64-out; optional affine-relu input; f32 or bf16 output ------
// grid (B, 50), block 128. weights optionally per-batch (wstride).
template <int AFFINE, int BF16OUT>
__global__ void conv1x1b_kernel(const float* __restrict__ in, const float* __restrict__ w,
                                int wstride, const float* __restrict__ bias,
                                const float* __restrict__ sc1, const float* __restrict__ sh1,
                                void* __restrict__ out) {
    __shared__ __align__(16) float wsm[4096];
    __shared__ float aff[128];
    int b = blockIdx.x;
    int n = blockIdx.y * 128 + threadIdx.x;
    const float* wb = w + (long)b * wstride;
    for (int i = threadIdx.x; i < 4096; i += 128) {
        int co = i >> 6, ci = i & 63;
        wsm[ci * 64 + co] = wb[i];
    }
    if (AFFINE) aff[threadIdx.x] = (threadIdx.x < 64) ? sc1[threadIdx.x] : sh1[threadIdx.x - 64];
    __syncthreads();
    float acc[64];
#pragma unroll
    for (int co = 0; co < 64; co++) acc[co] = bias ? bias[co] : 0.f;
    const float* inb = in + (long)b * 64 * Nv + n;
    const float4* wsm4 = (const float4*)wsm;
#pragma unroll 2
    for (int ci = 0; ci < 64; ci++) {
        float xv = inb[ci * Nv];
        if (AFFINE) xv = fmaxf(xv * aff[ci] + aff[64 + ci], 0.f);
#pragma unroll
        for (int c4 = 0; c4 < 16; c4++) {
            float4 w4 = wsm4[ci * 16 + c4];
            acc[c4 * 4 + 0] += w4.x * xv;
            acc[c4 * 4 + 1] += w4.y * xv;
            acc[c4 * 4 + 2] += w4.z * xv;
            acc[c4 * 4 + 3] += w4.w * xv;
        }
    }
    if (BF16OUT) {
        __nv_bfloat16* ob = (__nv_bfloat16*)out + (long)b * 64 * Nv + n;
#pragma unroll
        for (int co = 0; co < 64; co++) ob[(long)co * Nv] = __float2bfloat16(acc[co]);
    } else {
        float* ob = (float*)out + (long)b * 64 * Nv + n;
#pragma unroll
        for (int co = 0; co < 64; co++) ob[(long)co * Nv] = acc[co];
    }
}

// ---------------- CAM energy + softmax ----------------
__global__ void cam_kernel(const float* __restrict__ q, const float* __restrict__ k,
                           float* __restrict__ attn) {
    __shared__ __align__(16) float qsm[NQ];
    __shared__ float er[64];
    __shared__ float pe[64];
    int b = blockIdx.x >> 6, c = blockIdx.x & 63;
    const float* qr = q + (long)(b * 64 + c) * NQ;
    for (int i = threadIdx.x; i < NQ; i += 64) qsm[i] = qr[i];
    __syncthreads();
    int d = threadIdx.x;
    const float4* kr = (const float4*)(k + (long)(b * 64 + d) * NQ);
    const float4* q4 = (const float4*)qsm;
    float s = 0.f;
#pragma unroll 4
    for (int i = 0; i < NQ / 4; i++) {
        float4 kv = kr[i];
        float4 qv = q4[i];
        s += qv.x * kv.x + qv.y * kv.y + qv.z * kv.z + qv.w * kv.w;
    }
    er[d] = s;
    __syncthreads();
    float mn = er[0];
    for (int i = 1; i < 64; i++) mn = fminf(mn, er[i]);
    float p = __expf(mn - s);
    pe[d] = p;
    __syncthreads();
    float sum = 0.f;
    for (int i = 0; i < 64; i++) sum += pe[i];
    attn[(long)(b * 64 + c) * 64 + d] = p / sum;
}

// ---------------- PAM: flash attention via mma.sync bf16, 128-key tiles ----------------
// block 128 thr (4 warps x 16q = 64 q), grid (100, B).
__global__ void __launch_bounds__(128) pam_mma_kernel(
    const __nv_bfloat16* __restrict__ qg, const __nv_bfloat16* __restrict__ kg,
    const __nv_bfloat16* __restrict__ vg, float* __restrict__ sc) {
    __shared__ __align__(16) __nv_bfloat16 Qs[64 * 16];    // [q][e]
    __shared__ __align__(16) __nv_bfloat16 Ks[128 * 16];   // [j][e]
    __shared__ __align__(16) __nv_bfloat16 Vs[64 * 136];   // [c][j], stride 136 (conflict-free)
    int b = blockIdx.y;
    int q0 = blockIdx.x * 64;
    int t = threadIdx.x, w = t >> 5, lane = t & 31;
    int g = lane >> 2, ti = lane & 3;

    ((uint4*)Qs)[t] = ((const uint4*)(qg + ((long)b * Nv + q0) * 16))[t];
    __syncthreads();

    unsigned qa0, qa1, qa2, qa3;
    {
        const unsigned* qw = (const unsigned*)Qs;
        int r = w * 16 + g;
        qa0 = qw[r * 8 + ti];
        qa1 = qw[(r + 8) * 8 + ti];
        qa2 = qw[r * 8 + ti + 4];
        qa3 = qw[(r + 8) * 8 + ti + 4];
    }

    float o[8][4];
#pragma unroll
    for (int nc = 0; nc < 8; nc++) { o[nc][0] = o[nc][1] = o[nc][2] = o[nc][3] = 0.f; }
    float li_lo = 0.f, li_hi = 0.f, mi_lo = -1e30f, mi_hi = -1e30f;

    for (int j0 = 0; j0 < Nv; j0 += 128) {
        __syncthreads();
        // K tile: 128 rows x 2 uint4 = 256 chunks
        {
            const uint4* src = (const uint4*)(kg + ((long)b * Nv + j0) * 16);
            ((uint4*)Ks)[t] = src[t];
            ((uint4*)Ks)[t + 128] = src[t + 128];
        }
        // V tile: 64 c rows x 16 chunks
#pragma unroll
        for (int i = t; i < 1024; i += 128) {
            int c = i >> 4, h = i & 15;
            *(uint4*)(Vs + c * 136 + h * 8) =
                *(const uint4*)(vg + ((long)(b * 64 + c)) * Nv + j0 + h * 8);
        }
        __syncthreads();

#pragma unroll
        for (int sub = 0; sub < 2; sub++) {
            // QK: S[16q][64j] fragments
            float s[8][4];
            const unsigned* kw = (const unsigned*)Ks + sub * 512;
#pragma unroll
            for (int nt = 0; nt < 8; nt++) {
                int j = nt * 8 + g;
                unsigned b0 = kw[j * 8 + ti];
                unsigned b1 = kw[j * 8 + ti + 4];
                s[nt][0] = s[nt][1] = s[nt][2] = s[nt][3] = 0.f;
                mma16816(s[nt], qa0, qa1, qa2, qa3, b0, b1);
            }
            float mlo = s[0][0], mhi = s[0][2];
#pragma unroll
            for (int nt = 0; nt < 8; nt++) {
                mlo = fmaxf(mlo, fmaxf(s[nt][0], s[nt][1]));
                mhi = fmaxf(mhi, fmaxf(s[nt][2], s[nt][3]));
            }
            mlo = fmaxf(mlo, __shfl_xor_sync(0xffffffffu, mlo, 1));
            mlo = fmaxf(mlo, __shfl_xor_sync(0xffffffffu, mlo, 2));
            mhi = fmaxf(mhi, __shfl_xor_sync(0xffffffffu, mhi, 1));
            mhi = fmaxf(mhi, __shfl_xor_sync(0xffffffffu, mhi, 2));
            float nmlo = fmaxf(mi_lo, mlo), nmhi = fmaxf(mi_hi, mhi);
            float clo = ex2_(mi_lo - nmlo), chi = ex2_(mi_hi - nmhi);
            li_lo *= clo; li_hi *= chi;
#pragma unroll
            for (int nc = 0; nc < 8; nc++) {
                o[nc][0] *= clo; o[nc][1] *= clo; o[nc][2] *= chi; o[nc][3] *= chi;
            }
            unsigned pa[8][2];
#pragma unroll
            for (int nt = 0; nt < 8; nt++) {
                float p0 = ex2_(s[nt][0] - nmlo);
                float p1 = ex2_(s[nt][1] - nmlo);
                float p2 = ex2_(s[nt][2] - nmhi);
                float p3 = ex2_(s[nt][3] - nmhi);
                li_lo += p0 + p1;
                li_hi += p2 + p3;
                pa[nt][0] = pkbf(p0, p1);
                pa[nt][1] = pkbf(p2, p3);
            }
            mi_lo = nmlo; mi_hi = nmhi;

            // PV: O[16q][64c] += P * V^T
            const unsigned* vw = (const unsigned*)Vs + sub * 32;
#pragma unroll
            for (int nc = 0; nc < 8; nc++) {
                int c = nc * 8 + g;
                const unsigned* vr = vw + c * 68 + ti;
#pragma unroll
                for (int i = 0; i < 4; i++) {
                    unsigned b0 = vr[8 * i];
                    unsigned b1 = vr[8 * i + 4];
                    mma16816(o[nc], pa[2 * i][0], pa[2 * i][1],
                             pa[2 * i + 1][0], pa[2 * i + 1][1], b0, b1);
                }
            }
        }
    }
    li_lo += __shfl_xor_sync(0xffffffffu, li_lo, 1);
    li_lo += __shfl_xor_sync(0xffffffffu, li_lo, 2);
    li_hi += __shfl_xor_sync(0xffffffffu, li_hi, 1);
    li_hi += __shfl_xor_sync(0xffffffffu, li_hi, 2);
    float inv_lo = 1.f / li_lo, inv_hi = 1.f / li_hi;
    int q = q0 + w * 16 + g;
#pragma unroll
    for (int nc = 0; nc < 8; nc++) {
        int c = nc * 8 + ti * 2;
        sc[((long)(b * 64 + c)) * Nv + q] = o[nc][0] * inv_lo;
        sc[((long)(b * 64 + c + 1)) * Nv + q] = o[nc][1] * inv_lo;
        sc[((long)(b * 64 + c)) * Nv + q + 8] = o[nc][2] * inv_hi;
        sc[((long)(b * 64 + c + 1)) * Nv + q + 8] = o[nc][3] * inv_hi;
    }
}

// ---------------- feat_sum (f1 from raw t0 via BN1 affine-relu) + BN2 partial stats ----
__global__ void fsum_kernel(const float* __restrict__ sa, const float* __restrict__ sc,
                            const float* __restrict__ f1raw,
                            const float* __restrict__ sc1, const float* __restrict__ sh1,
                            const float* __restrict__ gamma1, const float* __restrict__ gamma2,
                            float* __restrict__ out,
                            float* __restrict__ ps, float* __restrict__ pss) {
    __shared__ float r1[256], r2[256];
    int bz = blockIdx.x;
    int b = bz >> 6, c = bz & 63;
    float g1 = gamma1[0], g2 = gamma2[0];
    float s1 = sc1[c], h1 = sh1[c];
    long base = (long)bz * Nv;
    const float4* sa4 = (const float4*)(sa + base);
    const float4* sc4 = (const float4*)(sc + base);
    const float4* f4 = (const float4*)(f1raw + base);
    float4* o4 = (float4*)(out + base);
    float s = 0.f, ss = 0.f;
    for (int i = threadIdx.x; i < 1600; i += 256) {
        float4 a = sa4[i], bb = sc4[i], f = f4[i];
        float4 v;
        v.x = g1 * a.x + g2 * bb.x + fmaxf(f.x * s1 + h1, 0.f);
        v.y = g1 * a.y + g2 * bb.y + fmaxf(f.y * s1 + h1, 0.f);
        v.z = g1 * a.z + g2 * bb.z + fmaxf(f.z * s1 + h1, 0.f);
        v.w = g1 * a.w + g2 * bb.w + fmaxf(f.w * s1 + h1, 0.f);
        o4[i] = v;
        s += v.x + v.y + v.z + v.w;
        ss += v.x * v.x + v.y * v.y + v.z * v.z + v.w * v.w;
    }
    int t = threadIdx.x;
    r1[t] = s; r2[t] = ss;
    __syncthreads();
    for (int st = 128; st > 0; st >>= 1) {
        if (t < st) { r1[t] += r1[t + st]; r2[t] += r2[t + st]; }
        __syncthreads();
    }
    if (t == 0) { ps[c * 64 + b] = r1[0]; pss[c * 64 + b] = r2[0]; }
}

// ---------------- host launch ----------------
extern "C" void kernel_launch(void* const* d_in, const int* in_sizes, int n_in,
                              void* d_out, int out_size) {
    const float* x     = (const float*)d_in[0];
    const float* Wc    = (const float*)d_in[1];
    const float* bn1g  = (const float*)d_in[2];
    const float* bn1b  = (const float*)d_in[3];
    const float* cqw   = (const float*)d_in[4];
    const float* cqb   = (const float*)d_in[5];
    const float* ckw   = (const float*)d_in[6];
    const float* ckb   = (const float*)d_in[7];
    const float* cvw   = (const float*)d_in[8];
    const float* cvb   = (const float*)d_in[9];
    const float* pqw   = (const float*)d_in[10];
    const float* pqb   = (const float*)d_in[11];
    const float* pkw   = (const float*)d_in[12];
    const float* pkb   = (const float*)d_in[13];
    const float* pvw   = (const float*)d_in[14];
    const float* pvb   = (const float*)d_in[15];
    const float* gamma1= (const float*)d_in[16];
    const float* gamma2= (const float*)d_in[17];
    const float* bn2g  = (const float*)d_in[18];
    const float* bn2b  = (const float*)d_in[19];
    const float* Wd    = (const float*)d_in[20];
    const float* bn3g  = (const float*)d_in[21];
    const float* bn3b  = (const float*)d_in[22];

    float* base = nullptr;
    cudaGetSymbolAddress((void**)&base, g_buf);
    float* t0    = base + OFF_T0;
    float* t1    = base + OFF_T1;
    float* vb    = base + OFF_VB;
    float* sab   = base + OFF_SAB;
    float* scb   = base + OFF_SCB;
    float* qb    = base + OFF_QB;
    float* kb    = base + OFF_KB;
    float* attn  = base + OFF_ATTN;
    float* ps    = base + OFF_PS;
    float* pss   = base + OFF_PSS;
    float* sc1   = base + OFF_SC1;
    float* sh1   = base + OFF_SH1;
    float* sc2   = base + OFF_SC2;
    float* sh2   = base + OFF_SH2;
    float* sc3   = base + OFF_SC3;
    float* sh3   = base + OFF_SH3;
    __nv_bfloat16* qg = (__nv_bfloat16*)(base + OFF_QG);
    __nv_bfloat16* kg = (__nv_bfloat16*)(base + OFF_KG);
    __nv_bfloat16* vg = (__nv_bfloat16*)(base + OFF_VG);

    const int C3SMEM = 32 * 324 * 4 + 64 * 9 * 8 * 8;  // 78336
    cudaFuncSetAttribute(conv3x3_kernel<0>, cudaFuncAttributeMaxDynamicSharedMemorySize, C3SMEM);
    cudaFuncSetAttribute(conv3x3_kernel<1>, cudaFuncAttributeMaxDynamicSharedMemorySize, C3SMEM);

    dim3 cgrid(5, 5, Bv * 4), cblk(16, 16);

    // stage 1: conv_c -> BN1 stats (apply folded into consumers)
    conv3x3_kernel<0><<<cgrid, cblk, C3SMEM>>>(x, Wc, nullptr, nullptr, t0);
    stats_kernel<<<Bv * Cv, 256>>>(t0, ps, pss);
    bn_finalize<<<1, 64>>>(ps, pss, bn1g, bn1b, sc1, sh1, 2);

    // projections (all read raw t0 + BN1 affine-relu inline)
    convqk_kernel<<<dim3(13, 8, Bv), 128>>>(t0, cqw, cqb, ckw, ckb, sc1, sh1, qb, kb);
    convqk1x1_kernel<<<dim3(Bv, 50), 128>>>(t0, pqw, pqb, pkw, pkb, sc1, sh1, qg, kg);
    conv1x1b_kernel<1, 0><<<dim3(Bv, 50), 128>>>(t0, cvw, 0, cvb, sc1, sh1, vb);
    conv1x1b_kernel<1, 1><<<dim3(Bv, 50), 128>>>(t0, pvw, 0, pvb, sc1, sh1, vg);

    // CAM
    cam_kernel<<<Bv * Cv, 64>>>(qb, kb, attn);
    conv1x1b_kernel<0, 0><<<dim3(Bv, 50), 128>>>(vb, attn, 4096, nullptr, nullptr, nullptr, sab);

    // PAM (flash attention via tensor cores)
    pam_mma_kernel<<<dim3(100, Bv), 128>>>(qg, kg, vg, scb);

    // combine (in-place on t0) + BN2 (folded into conv_d input) -> conv_d -> BN3 -> ReLU
    fsum_kernel<<<Bv * Cv, 256>>>(sab, scb, t0, sc1, sh1, gamma1, gamma2, t0, ps, pss);
    bn_finalize<<<1, 64>>>(ps, pss, bn2g, bn2b, sc2, sh2, 2);
    conv3x3_kernel<1><<<cgrid, cblk, C3SMEM>>>(t0, Wd, sc2, sh2, t1);
    stats_kernel<<<Bv * Cv, 256>>>(t1, ps, pss);
    bn_finalize<<<1, 64>>>(ps, pss, bn3g, bn3b, sc3, sh3, 2);
    bn_apply_kernel<<<800, 256>>>((const float4*)t1, (float4*)d_out, sc3, sh3);
}

// round 8
// speedup vs baseline: 4.4095x; 1.0554x over previous
#include <cuda_runtime.h>
#include <cuda_bf16.h>
#include <math.h>

#define Bv 2
#define Cv 64
#define Hv 80
#define Wv 80
#define Nv 6400
#define NQ 1600
#define NHWf 12800.0f
#define EPSV 1e-5f
#define L2E 1.44269504088896f

typedef unsigned long long ull;

// ---------------- packed helpers ----------------
__device__ __forceinline__ ull pk2(float lo, float hi) {
    ull r; asm("mov.b64 %0,{%1,%2};" : "=l"(r) : "f"(lo), "f"(hi)); return r;
}
__device__ __forceinline__ void upk2(ull v, float& lo, float& hi) {
    asm("mov.b64 {%0,%1},%2;" : "=f"(lo), "=f"(hi) : "l"(v));
}
__device__ __forceinline__ ull fma2_(ull a, ull b, ull c) {
    ull d; asm("fma.rn.f32x2 %0,%1,%2,%3;" : "=l"(d) : "l"(a), "l"(b), "l"(c)); return d;
}
__device__ __forceinline__ float ex2_(float x) {
    float y; asm("ex2.approx.ftz.f32 %0,%1;" : "=f"(y) : "f"(x)); return y;
}
__device__ __forceinline__ unsigned pkbf(float lo, float hi) {
    unsigned d; asm("cvt.rn.bf16x2.f32 %0,%1,%2;" : "=r"(d) : "f"(hi), "f"(lo)); return d;
}
__device__ __forceinline__ void mma16816(float* c, unsigned a0, unsigned a1, unsigned a2,
                                         unsigned a3, unsigned b0, unsigned b1) {
    asm("mma.sync.aligned.m16n8k16.row.col.f32.bf16.bf16.f32 "
        "{%0,%1,%2,%3},{%4,%5,%6,%7},{%8,%9},{%0,%1,%2,%3};"
        : "+f"(c[0]), "+f"(c[1]), "+f"(c[2]), "+f"(c[3])
        : "r"(a0), "r"(a1), "r"(a2), "r"(a3), "r"(b0), "r"(b1));
}

// ---------------- scratch ----------------
#define OFF_T0     0
#define OFF_T1     (OFF_T0   + Bv*Cv*Nv)
#define OFF_VB     (OFF_T1   + Bv*Cv*Nv)
#define OFF_SAB    (OFF_VB   + Bv*Cv*Nv)
#define OFF_SCB    (OFF_SAB  + Bv*Cv*Nv)
#define OFF_QB     (OFF_SCB  + Bv*Cv*Nv)
#define OFF_KB     (OFF_QB   + Bv*Cv*NQ)
#define OFF_ATTN   (OFF_KB   + Bv*Cv*NQ)
#define OFF_PS     (OFF_ATTN + Bv*Cv*Cv)
#define OFF_PSS    (OFF_PS   + 64*64)
#define OFF_SC1    (OFF_PSS  + 64*64)
#define OFF_SH1    (OFF_SC1  + 64)
#define OFF_SC2    (OFF_SH1  + 64)
#define OFF_SH2    (OFF_SC2  + 64)
#define OFF_SC3    (OFF_SH2  + 64)
#define OFF_SH3    (OFF_SC3  + 64)
#define OFF_QG     (OFF_SH3  + 64)          /* bf16 [B][N][16] */
#define OFF_KG     (OFF_QG   + Bv*Nv*8)
#define OFF_VG     (OFF_KG   + Bv*Nv*8)     /* bf16 [B][C][N] */
#define BUF_TOTAL  (OFF_VG   + Bv*Cv*Nv/2)

__device__ __align__(16) float g_buf[BUF_TOTAL];

// ---------------- conv3x3 (pad=1, no bias) + fused per-block BN stats ------------------
// grid (5,5, B*4), block (16,16). slot = b*25 + tile. 16 co per block.
template <int AFFINE>
__global__ void conv3x3_kernel(const float* __restrict__ in, const float* __restrict__ w,
                               const float* __restrict__ scale, const float* __restrict__ shift,
                               float* __restrict__ out,
                               float* __restrict__ ps, float* __restrict__ pss) {
    extern __shared__ float sm[];
    float* tile = sm;                                   // 32*324
    ull* w2 = (ull*)(sm + 32 * 324);                    // [ci*9+tap][8] co-pairs (all 64 ci)
    __shared__ float aff[128];
    __shared__ float red[8][32];
    int bz = blockIdx.z;
    int b = bz >> 2, co0 = (bz & 3) * 16;
    int t = threadIdx.y * 16 + threadIdx.x;

    float* wflat = (float*)w2;
    for (int i = t; i < 9216; i += 256) {
        int co = i & 15, r = i >> 4;
        wflat[r * 16 + co] = w[(co0 + co) * 576 + r];
    }
    if (AFFINE && t < 128) aff[t] = (t < 64) ? scale[t] : shift[t - 64];

    int oy0 = blockIdx.y * 16, ox0 = blockIdx.x * 16;
    const float* inb = in + (long)b * Cv * Nv;

    ull acc2[8];
#pragma unroll
    for (int c2 = 0; c2 < 8; c2++) acc2[c2] = pk2(0.f, 0.f);

    for (int chunk = 0; chunk < 2; chunk++) {
        int cbase = chunk * 32;
        __syncthreads();
        for (int i = t; i < 32 * 324; i += 256) {
            int ci = i / 324;
            int pos = i - ci * 324;
            int r = pos / 18, c2 = pos - r * 18;
            int gy = oy0 + r - 1, gx = ox0 + c2 - 1;
            float v = 0.f;
            if (gy >= 0 && gy < Hv && gx >= 0 && gx < Wv) {
                v = inb[(cbase + ci) * Nv + gy * Wv + gx];
                if (AFFINE) v = v * aff[cbase + ci] + aff[64 + cbase + ci];
            }
            tile[i] = v;
        }
        __syncthreads();

        for (int ci = 0; ci < 32; ci++) {
            const float* tp = tile + ci * 324 + threadIdx.y * 18 + threadIdx.x;
            float x[9];
#pragma unroll
            for (int ky = 0; ky < 3; ky++)
#pragma unroll
                for (int kx = 0; kx < 3; kx++) x[ky * 3 + kx] = tp[ky * 18 + kx];
            const ull* wr = w2 + (long)(cbase + ci) * 72;
#pragma unroll
            for (int tap = 0; tap < 9; tap++) {
                ull xd = pk2(x[tap], x[tap]);
#pragma unroll
                for (int c2 = 0; c2 < 8; c2++)
                    acc2[c2] = fma2_(xd, wr[tap * 8 + c2], acc2[c2]);
            }
        }
    }
    long obase = ((long)b * 64 + co0) * Nv + (oy0 + threadIdx.y) * Wv + ox0 + threadIdx.x;
    float v[16], q[16];
#pragma unroll
    for (int c2 = 0; c2 < 8; c2++) {
        float lo, hi;
        upk2(acc2[c2], lo, hi);
        out[obase + (long)(2 * c2) * Nv] = lo;
        out[obase + (long)(2 * c2 + 1) * Nv] = hi;
        v[2 * c2] = lo; v[2 * c2 + 1] = hi;
        q[2 * c2] = lo * lo; q[2 * c2 + 1] = hi * hi;
    }
    // warp reduce 16 sums + 16 sumsqs
#pragma unroll
    for (int c = 0; c < 16; c++) {
#pragma unroll
        for (int off = 16; off > 0; off >>= 1) {
            v[c] += __shfl_xor_sync(0xffffffffu, v[c], off);
            q[c] += __shfl_xor_sync(0xffffffffu, q[c], off);
        }
    }
    int warp = t >> 5, lane = t & 31;
    if (lane < 16) red[warp][lane] = v[lane];
    else red[warp][lane] = q[lane - 16];
    __syncthreads();
    if (t < 32) {
        float s = 0.f;
#pragma unroll
        for (int wi = 0; wi < 8; wi++) s += red[wi][t];
        int slot = b * 25 + blockIdx.y * 5 + blockIdx.x;
        if (t < 16) ps[(co0 + t) * 64 + slot] = s;
        else pss[(co0 + t - 16) * 64 + slot] = s;
    }
}

// ---------------- BN finalize ----------------
__global__ void bn_finalize(const float* __restrict__ ps, const float* __restrict__ pss,
                            const float* __restrict__ g, const float* __restrict__ bb,
                            float* __restrict__ scale, float* __restrict__ shift, int nslots) {
    int c = threadIdx.x;
    float s = 0.f, ss = 0.f;
    for (int i = 0; i < nslots; i++) { s += ps[c * 64 + i]; ss += pss[c * 64 + i]; }
    float m = s / NHWf;
    float var = ss / NHWf - m * m;
    float rs = rsqrtf(var + EPSV);
    float sc = g[c] * rs;
    scale[c] = sc;
    shift[c] = bb[c] - m * sc;
}

// ---------------- BN apply (float4, +relu) — final output only ----------------
__global__ void bn_apply_kernel(const float4* __restrict__ in, float4* __restrict__ out,
                                const float* __restrict__ scale, const float* __restrict__ shift) {
    int i = blockIdx.x * 256 + threadIdx.x;
    int c = (i / 1600) & 63;
    float sc = scale[c], sh = shift[c];
    float4 v = in[i];
    v.x = fmaxf(v.x * sc + sh, 0.f);
    v.y = fmaxf(v.y * sc + sh, 0.f);
    v.z = fmaxf(v.z * sc + sh, 0.f);
    v.w = fmaxf(v.w * sc + sh, 0.f);
    out[i] = v;
}

// ---------------- fused conv2x2 stride2 (q and k), affine-relu input, 8-co groups ------
// grid (13, 16, B): y = conv*8 + cogrp(8 co). block 128.
__global__ void convqk_kernel(const float* __restrict__ in,
                              const float* __restrict__ wq, const float* __restrict__ bq,
                              const float* __restrict__ wk, const float* __restrict__ bk,
                              const float* __restrict__ sc1, const float* __restrict__ sh1,
                              float* __restrict__ outq, float* __restrict__ outk) {
    __shared__ __align__(16) float wsm[2048];  // [ci*4+tap][8co]
    __shared__ float aff[128];
    int conv = blockIdx.y >> 3;
    int co0 = (blockIdx.y & 7) * 8;
    int b = blockIdx.z;
    const float* w = conv ? wk : wq;
    const float* bias = conv ? bk : bq;
    float* out = conv ? outk : outq;

    for (int i = threadIdx.x; i < 2048; i += 128) {
        int co = i & 7, r = i >> 3;
        wsm[r * 8 + co] = w[(co0 + co) * 256 + r];
    }
    aff[threadIdx.x] = (threadIdx.x < 64) ? sc1[threadIdx.x] : sh1[threadIdx.x - 64];
    __syncthreads();

    int p = blockIdx.x * 128 + threadIdx.x;
    if (p >= NQ) return;
    int oy = p / 40, ox = p % 40;
    const float* inb = in + (long)b * Cv * Nv + (2 * oy) * Wv + 2 * ox;

    ull acc2[4];
    const ull* w2 = (const ull*)wsm;
#pragma unroll
    for (int c2 = 0; c2 < 4; c2++) acc2[c2] = pk2(bias[co0 + 2 * c2], bias[co0 + 2 * c2 + 1]);

#pragma unroll 4
    for (int ci = 0; ci < 64; ci++) {
        float s = aff[ci], h = aff[64 + ci];
        float2 a = *(const float2*)(inb + ci * Nv);
        float2 bb2 = *(const float2*)(inb + ci * Nv + Wv);
        float v0 = fmaxf(a.x * s + h, 0.f), v1 = fmaxf(a.y * s + h, 0.f);
        float v2 = fmaxf(bb2.x * s + h, 0.f), v3 = fmaxf(bb2.y * s + h, 0.f);
        ull x0 = pk2(v0, v0), x1 = pk2(v1, v1);
        ull x2 = pk2(v2, v2), x3 = pk2(v3, v3);
        const ull* wr = w2 + ci * 16;   // 4 taps * 4 pairs
#pragma unroll
        for (int c2 = 0; c2 < 4; c2++) {
            ull a2 = fma2_(x0, wr[c2], acc2[c2]);
            a2 = fma2_(x1, wr[4 + c2], a2);
            a2 = fma2_(x2, wr[8 + c2], a2);
            acc2[c2] = fma2_(x3, wr[12 + c2], a2);
        }
    }
    long obase = ((long)b * 64 + co0) * NQ + p;
#pragma unroll
    for (int c2 = 0; c2 < 4; c2++) {
        float lo, hi;
        upk2(acc2[c2], lo, hi);
        out[obase + (long)(2 * c2) * NQ] = lo;
        out[obase + (long)(2 * c2 + 1) * NQ] = hi;
    }
}

// ---------------- pq/pk 1x1 conv (8 outs), affine-relu input, bf16 [n][16] out ---------
// grid (B, 50, 2): z = which conv. block 128.
__global__ void convqk1x1_kernel(const float* __restrict__ in,
                                 const float* __restrict__ wq, const float* __restrict__ bq,
                                 const float* __restrict__ wk, const float* __restrict__ bk,
                                 const float* __restrict__ sc1, const float* __restrict__ sh1,
                                 __nv_bfloat16* __restrict__ qg, __nv_bfloat16* __restrict__ kg) {
    __shared__ __align__(16) float wsm[512];  // [ci*8+co]
    __shared__ float aff[128];
    int b = blockIdx.x;
    int which = blockIdx.z;
    const float* w = which ? wk : wq;
    const float* bias = which ? bk : bq;
    __nv_bfloat16* outg = which ? kg : qg;
    float osc = which ? 1.f : L2E;
    int n = blockIdx.y * 128 + threadIdx.x;
    for (int i = threadIdx.x; i < 512; i += 128) {
        int co = i >> 6, ci = i & 63;
        wsm[ci * 8 + co] = w[i];
    }
    aff[threadIdx.x] = (threadIdx.x < 64) ? sc1[threadIdx.x] : sh1[threadIdx.x - 64];
    __syncthreads();
    float aq[8];
#pragma unroll
    for (int j = 0; j < 8; j++) aq[j] = bias[j];
    const float* inb = in + (long)b * 64 * Nv + n;
    const float4* w4p = (const float4*)wsm;
#pragma unroll 4
    for (int ci = 0; ci < 64; ci++) {
        float xv = fmaxf(inb[ci * Nv] * aff[ci] + aff[64 + ci], 0.f);
#pragma unroll
        for (int c4 = 0; c4 < 2; c4++) {
            float4 w4 = w4p[ci * 2 + c4];
            aq[c4 * 4 + 0] += w4.x * xv; aq[c4 * 4 + 1] += w4.y * xv;
            aq[c4 * 4 + 2] += w4.z * xv; aq[c4 * 4 + 3] += w4.w * xv;
        }
    }
    uint4* qd = (uint4*)(outg + ((long)b * Nv + n) * 16);
    qd[0] = make_uint4(pkbf(aq[0] * osc, aq[1] * osc), pkbf(aq[2] * osc, aq[3] * osc),
                       pkbf(aq[4] * osc, aq[5] * osc), pkbf(aq[6] * osc, aq[7] * osc));
    qd[1] = make_uint4(0u, 0u, 0u, 0u);
}

// ---------------- conv1x1, 16-co groups; optional affine-relu input; f32/bf16 out ------
// grid (B, 50, 4): z = cogroup. block 128. weights optionally per-batch (wstride).
template <int AFFINE, int BF16OUT>
__global__ void conv1x1g_kernel(const float* __restrict__ in, const float* __restrict__ w,
                                int wstride, const float* __restrict__ bias,
                                const float* __restrict__ sc1, const float* __restrict__ sh1,
                                void* __restrict__ out) {
    __shared__ __align__(16) float wsm[1024];
    __shared__ float aff[128];
    int b = blockIdx.x;
    int co0 = blockIdx.z * 16;
    int n = blockIdx.y * 128 + threadIdx.x;
    const float* wb = w + (long)b * wstride;
    for (int i = threadIdx.x; i < 1024; i += 128) {
        int co = i >> 6, ci = i & 63;
        wsm[ci * 16 + co] = wb[(co0 + co) * 64 + ci];
    }
    if (AFFINE) aff[threadIdx.x] = (threadIdx.x < 64) ? sc1[threadIdx.x] : sh1[threadIdx.x - 64];
    __syncthreads();
    float acc[16];
#pragma unroll
    for (int co = 0; co < 16; co++) acc[co] = bias ? bias[co0 + co] : 0.f;
    const float* inb = in + (long)b * 64 * Nv + n;
    const float4* wsm4 = (const float4*)wsm;
#pragma unroll 4
    for (int ci = 0; ci < 64; ci++) {
        float xv = inb[ci * Nv];
        if (AFFINE) xv = fmaxf(xv * aff[ci] + aff[64 + ci], 0.f);
#pragma unroll
        for (int c4 = 0; c4 < 4; c4++) {
            float4 w4 = wsm4[ci * 4 + c4];
            acc[c4 * 4 + 0] += w4.x * xv;
            acc[c4 * 4 + 1] += w4.y * xv;
            acc[c4 * 4 + 2] += w4.z * xv;
            acc[c4 * 4 + 3] += w4.w * xv;
        }
    }
    if (BF16OUT) {
        __nv_bfloat16* ob = (__nv_bfloat16*)out + ((long)b * 64 + co0) * Nv + n;
#pragma unroll
        for (int co = 0; co < 16; co++) ob[(long)co * Nv] = __float2bfloat16(acc[co]);
    } else {
        float* ob = (float*)out + ((long)b * 64 + co0) * Nv + n;
#pragma unroll
        for (int co = 0; co < 16; co++) ob[(long)co * Nv] = acc[co];
    }
}

// ---------------- CAM energy + softmax ----------------
__global__ void cam_kernel(const float* __restrict__ q, const float* __restrict__ k,
                           float* __restrict__ attn) {
    __shared__ __align__(16) float qsm[NQ];
    __shared__ float er[64];
    __shared__ float pe[64];
    int b = blockIdx.x >> 6, c = blockIdx.x & 63;
    const float* qr = q + (long)(b * 64 + c) * NQ;
    for (int i = threadIdx.x; i < NQ; i += 64) qsm[i] = qr[i];
    __syncthreads();
    int d = threadIdx.x;
    const float4* kr = (const float4*)(k + (long)(b * 64 + d) * NQ);
    const float4* q4 = (const float4*)qsm;
    float s = 0.f;
#pragma unroll 4
    for (int i = 0; i < NQ / 4; i++) {
        float4 kv = kr[i];
        float4 qv = q4[i];
        s += qv.x * kv.x + qv.y * kv.y + qv.z * kv.z + qv.w * kv.w;
    }
    er[d] = s;
    __syncthreads();
    float mn = er[0];
    for (int i = 1; i < 64; i++) mn = fminf(mn, er[i]);
    float p = __expf(mn - s);
    pe[d] = p;
    __syncthreads();
    float sum = 0.f;
    for (int i = 0; i < 64; i++) sum += pe[i];
    attn[(long)(b * 64 + c) * 64 + d] = p / sum;
}

// ---------------- PAM: flash attention via mma.sync bf16, 128-key tiles ----------------
__global__ void __launch_bounds__(128) pam_mma_kernel(
    const __nv_bfloat16* __restrict__ qg, const __nv_bfloat16* __restrict__ kg,
    const __nv_bfloat16* __restrict__ vg, float* __restrict__ sc) {
    __shared__ __align__(16) __nv_bfloat16 Qs[64 * 16];
    __shared__ __align__(16) __nv_bfloat16 Ks[128 * 16];
    __shared__ __align__(16) __nv_bfloat16 Vs[64 * 136];
    int b = blockIdx.y;
    int q0 = blockIdx.x * 64;
    int t = threadIdx.x, w = t >> 5, lane = t & 31;
    int g = lane >> 2, ti = lane & 3;

    ((uint4*)Qs)[t] = ((const uint4*)(qg + ((long)b * Nv + q0) * 16))[t];
    __syncthreads();

    unsigned qa0, qa1, qa2, qa3;
    {
        const unsigned* qw = (const unsigned*)Qs;
        int r = w * 16 + g;
        qa0 = qw[r * 8 + ti];
        qa1 = qw[(r + 8) * 8 + ti];
        qa2 = qw[r * 8 + ti + 4];
        qa3 = qw[(r + 8) * 8 + ti + 4];
    }

    float o[8][4];
#pragma unroll
    for (int nc = 0; nc < 8; nc++) { o[nc][0] = o[nc][1] = o[nc][2] = o[nc][3] = 0.f; }
    float li_lo = 0.f, li_hi = 0.f, mi_lo = -1e30f, mi_hi = -1e30f;

    for (int j0 = 0; j0 < Nv; j0 += 128) {
        __syncthreads();
        {
            const uint4* src = (const uint4*)(kg + ((long)b * Nv + j0) * 16);
            ((uint4*)Ks)[t] = src[t];
            ((uint4*)Ks)[t + 128] = src[t + 128];
        }
#pragma unroll
        for (int i = t; i < 1024; i += 128) {
            int c = i >> 4, h = i & 15;
            *(uint4*)(Vs + c * 136 + h * 8) =
                *(const uint4*)(vg + ((long)(b * 64 + c)) * Nv + j0 + h * 8);
        }
        __syncthreads();

#pragma unroll
        for (int sub = 0; sub < 2; sub++) {
            float s[8][4];
            const unsigned* kw = (const unsigned*)Ks + sub * 512;
#pragma unroll
            for (int nt = 0; nt < 8; nt++) {
                int j = nt * 8 + g;
                unsigned b0 = kw[j * 8 + ti];
                unsigned b1 = kw[j * 8 + ti + 4];
                s[nt][0] = s[nt][1] = s[nt][2] = s[nt][3] = 0.f;
                mma16816(s[nt], qa0, qa1, qa2, qa3, b0, b1);
            }
            float mlo = s[0][0], mhi = s[0][2];
#pragma unroll
            for (int nt = 0; nt < 8; nt++) {
                mlo = fmaxf(mlo, fmaxf(s[nt][0], s[nt][1]));
                mhi = fmaxf(mhi, fmaxf(s[nt][2], s[nt][3]));
            }
            mlo = fmaxf(mlo, __shfl_xor_sync(0xffffffffu, mlo, 1));
            mlo = fmaxf(mlo, __shfl_xor_sync(0xffffffffu, mlo, 2));
            mhi = fmaxf(mhi, __shfl_xor_sync(0xffffffffu, mhi, 1));
            mhi = fmaxf(mhi, __shfl_xor_sync(0xffffffffu, mhi, 2));
            float nmlo = fmaxf(mi_lo, mlo), nmhi = fmaxf(mi_hi, mhi);
            float clo = ex2_(mi_lo - nmlo), chi = ex2_(mi_hi - nmhi);
            li_lo *= clo; li_hi *= chi;
#pragma unroll
            for (int nc = 0; nc < 8; nc++) {
                o[nc][0] *= clo; o[nc][1] *= clo; o[nc][2] *= chi; o[nc][3] *= chi;
            }
            unsigned pa[8][2];
#pragma unroll
            for (int nt = 0; nt < 8; nt++) {
                float p0 = ex2_(s[nt][0] - nmlo);
                float p1 = ex2_(s[nt][1] - nmlo);
                float p2 = ex2_(s[nt][2] - nmhi);
                float p3 = ex2_(s[nt][3] - nmhi);
                li_lo += p0 + p1;
                li_hi += p2 + p3;
                pa[nt][0] = pkbf(p0, p1);
                pa[nt][1] = pkbf(p2, p3);
            }
            mi_lo = nmlo; mi_hi = nmhi;

            const unsigned* vw = (const unsigned*)Vs + sub * 32;
#pragma unroll
            for (int nc = 0; nc < 8; nc++) {
                int c = nc * 8 + g;
                const unsigned* vr = vw + c * 68 + ti;
#pragma unroll
                for (int i = 0; i < 4; i++) {
                    unsigned b0 = vr[8 * i];
                    unsigned b1 = vr[8 * i + 4];
                    mma16816(o[nc], pa[2 * i][0], pa[2 * i][1],
                             pa[2 * i + 1][0], pa[2 * i + 1][1], b0, b1);
                }
            }
        }
    }
    li_lo += __shfl_xor_sync(0xffffffffu, li_lo, 1);
    li_lo += __shfl_xor_sync(0xffffffffu, li_lo, 2);
    li_hi += __shfl_xor_sync(0xffffffffu, li_hi, 1);
    li_hi += __shfl_xor_sync(0xffffffffu, li_hi, 2);
    float inv_lo = 1.f / li_lo, inv_hi = 1.f / li_hi;
    int q = q0 + w * 16 + g;
#pragma unroll
    for (int nc = 0; nc < 8; nc++) {
        int c = nc * 8 + ti * 2;
        sc[((long)(b * 64 + c)) * Nv + q] = o[nc][0] * inv_lo;
        sc[((long)(b * 64 + c + 1)) * Nv + q] = o[nc][1] * inv_lo;
        sc[((long)(b * 64 + c)) * Nv + q + 8] = o[nc][2] * inv_hi;
        sc[((long)(b * 64 + c + 1)) * Nv + q + 8] = o[nc][3] * inv_hi;
    }
}

// ---------------- feat_sum (f1 from raw t0 via BN1 affine-relu) + BN2 partial stats ----
__global__ void fsum_kernel(const float* __restrict__ sa, const float* __restrict__ sc,
                            const float* __restrict__ f1raw,
                            const float* __restrict__ sc1, const float* __restrict__ sh1,
                            const float* __restrict__ gamma1, const float* __restrict__ gamma2,
                            float* __restrict__ out,
                            float* __restrict__ ps, float* __restrict__ pss) {
    __shared__ float r1[256], r2[256];
    int bz = blockIdx.x;
    int b = bz >> 6, c = bz & 63;
    float g1 = gamma1[0], g2 = gamma2[0];
    float s1 = sc1[c], h1 = sh1[c];
    long base = (long)bz * Nv;
    const float4* sa4 = (const float4*)(sa + base);
    const float4* sc4 = (const float4*)(sc + base);
    const float4* f4 = (const float4*)(f1raw + base);
    float4* o4 = (float4*)(out + base);
    float s = 0.f, ss = 0.f;
    for (int i = threadIdx.x; i < 1600; i += 256) {
        float4 a = sa4[i], bb = sc4[i], f = f4[i];
        float4 v;
        v.x = g1 * a.x + g2 * bb.x + fmaxf(f.x * s1 + h1, 0.f);
        v.y = g1 * a.y + g2 * bb.y + fmaxf(f.y * s1 + h1, 0.f);
        v.z = g1 * a.z + g2 * bb.z + fmaxf(f.z * s1 + h1, 0.f);
        v.w = g1 * a.w + g2 * bb.w + fmaxf(f.w * s1 + h1, 0.f);
        o4[i] = v;
        s += v.x + v.y + v.z + v.w;
        ss += v.x * v.x + v.y * v.y + v.z * v.z + v.w * v.w;
    }
    int t = threadIdx.x;
    r1[t] = s; r2[t] = ss;
    __syncthreads();
    for (int st = 128; st > 0; st >>= 1) {
        if (t < st) { r1[t] += r1[t + st]; r2[t] += r2[t + st]; }
        __syncthreads();
    }
    if (t == 0) { ps[c * 64 + b] = r1[0]; pss[c * 64 + b] = r2[0]; }
}

// ---------------- host launch ----------------
extern "C" void kernel_launch(void* const* d_in, const int* in_sizes, int n_in,
                              void* d_out, int out_size) {
    const float* x     = (const float*)d_in[0];
    const float* Wc    = (const float*)d_in[1];
    const float* bn1g  = (const float*)d_in[2];
    const float* bn1b  = (const float*)d_in[3];
    const float* cqw   = (const float*)d_in[4];
    const float* cqb   = (const float*)d_in[5];
    const float* ckw   = (const float*)d_in[6];
    const float* ckb   = (const float*)d_in[7];
    const float* cvw   = (const float*)d_in[8];
    const float* cvb   = (const float*)d_in[9];
    const float* pqw   = (const float*)d_in[10];
    const float* pqb   = (const float*)d_in[11];
    const float* pkw   = (const float*)d_in[12];
    const float* pkb   = (const float*)d_in[13];
    const float* pvw   = (const float*)d_in[14];
    const float* pvb   = (const float*)d_in[15];
    const float* gamma1= (const float*)d_in[16];
    const float* gamma2= (const float*)d_in[17];
    const float* bn2g  = (const float*)d_in[18];
    const float* bn2b  = (const float*)d_in[19];
    const float* Wd    = (const float*)d_in[20];
    const float* bn3g  = (const float*)d_in[21];
    const float* bn3b  = (const float*)d_in[22];

    float* base = nullptr;
    cudaGetSymbolAddress((void**)&base, g_buf);
    float* t0    = base + OFF_T0;
    float* t1    = base + OFF_T1;
    float* vb    = base + OFF_VB;
    float* sab   = base + OFF_SAB;
    float* scb   = base + OFF_SCB;
    float* qb    = base + OFF_QB;
    float* kb    = base + OFF_KB;
    float* attn  = base + OFF_ATTN;
    float* ps    = base + OFF_PS;
    float* pss   = base + OFF_PSS;
    float* sc1   = base + OFF_SC1;
    float* sh1   = base + OFF_SH1;
    float* sc2   = base + OFF_SC2;
    float* sh2   = base + OFF_SH2;
    float* sc3   = base + OFF_SC3;
    float* sh3   = base + OFF_SH3;
    __nv_bfloat16* qg = (__nv_bfloat16*)(base + OFF_QG);
    __nv_bfloat16* kg = (__nv_bfloat16*)(base + OFF_KG);
    __nv_bfloat16* vg = (__nv_bfloat16*)(base + OFF_VG);

    const int C3SMEM = 32 * 324 * 4 + 64 * 9 * 8 * 8;  // 78336
    cudaFuncSetAttribute(conv3x3_kernel<0>, cudaFuncAttributeMaxDynamicSharedMemorySize, C3SMEM);
    cudaFuncSetAttribute(conv3x3_kernel<1>, cudaFuncAttributeMaxDynamicSharedMemorySize, C3SMEM);

    dim3 cgrid(5, 5, Bv * 4), cblk(16, 16);

    // stage 1: conv_c (+fused BN1 stats) -> finalize
    conv3x3_kernel<0><<<cgrid, cblk, C3SMEM>>>(x, Wc, nullptr, nullptr, t0, ps, pss);
    bn_finalize<<<1, 64>>>(ps, pss, bn1g, bn1b, sc1, sh1, 50);

    // projections (all read raw t0 + BN1 affine-relu inline)
    convqk_kernel<<<dim3(13, 16, Bv), 128>>>(t0, cqw, cqb, ckw, ckb, sc1, sh1, qb, kb);
    convqk1x1_kernel<<<dim3(Bv, 50, 2), 128>>>(t0, pqw, pqb, pkw, pkb, sc1, sh1, qg, kg);
    conv1x1g_kernel<1, 0><<<dim3(Bv, 50, 4), 128>>>(t0, cvw, 0, cvb, sc1, sh1, vb);
    conv1x1g_kernel<1, 1><<<dim3(Bv, 50, 4), 128>>>(t0, pvw, 0, pvb, sc1, sh1, vg);

    // CAM
    cam_kernel<<<Bv * Cv, 64>>>(qb, kb, attn);
    conv1x1g_kernel<0, 0><<<dim3(Bv, 50, 4), 128>>>(vb, attn, 4096, nullptr, nullptr, nullptr,
                                                    sab);

    // PAM (flash attention via tensor cores)
    pam_mma_kernel<<<dim3(100, Bv), 128>>>(qg, kg, vg, scb);

    // combine (in-place on t0) + BN2 -> conv_d (+fused BN3 stats) -> finalize -> apply
    fsum_kernel<<<Bv * Cv, 256>>>(sab, scb, t0, sc1, sh1, gamma1, gamma2, t0, ps, pss);
    bn_finalize<<<1, 64>>>(ps, pss, bn2g, bn2b, sc2, sh2, 2);
    conv3x3_kernel<1><<<cgrid, cblk, C3SMEM>>>(t0, Wd, sc2, sh2, t1, ps, pss);
    bn_finalize<<<1, 64>>>(ps, pss, bn3g, bn3b, sc3, sh3, 50);
    bn_apply_kernel<<<800, 256>>>((const float4*)t1, (float4*)d_out, sc3, sh3);
}